// round 1
// baseline (speedup 1.0000x reference)
#include <cuda_runtime.h>
#include <cuda_bf16.h>
#include <math.h>

// Problem constants
#define BATCH 2
#define SEQ   2048
#define DIM   1024
#define HEADS 16
#define DHEAD 64
#define INNER 1024              // HEADS*DHEAD
#define QKV_COLS 3072           // 3*INNER
#define MROWS 4096              // BATCH*SEQ
#define ATT_SCALE 0.125f        // 64^-0.5

// Scratch (device globals — no cudaMalloc allowed)
__device__ float g_qkv[(size_t)BATCH * SEQ * QKV_COLS];   // 50.3 MB
__device__ float g_att[(size_t)BATCH * SEQ * INNER];      // 16.8 MB

// ---------------------------------------------------------------------------
// SGEMM: C[M,N] = A[M,K] @ B[K,N], row-major fp32.
// 128x128 block tile, BK=8, 256 threads, 8x8 per thread (2x2 quadrants of 4x4).
// Requires M%128==0, N%128==0, K%8==0 (true for all uses here).
// ---------------------------------------------------------------------------
__global__ __launch_bounds__(256, 2)
void sgemm_kernel(const float* __restrict__ A, const float* __restrict__ B,
                  float* __restrict__ C, int M, int N, int K)
{
    __shared__ float As[8][128];   // transposed: As[k][m]
    __shared__ float Bs[8][128];   // Bs[k][n]

    const int tid = threadIdx.x;
    const int tx  = tid & 15;      // 0..15
    const int ty  = tid >> 4;      // 0..15
    const int row0 = blockIdx.y * 128;
    const int col0 = blockIdx.x * 128;

    // load mapping
    const int arow  = tid >> 1;         // 0..127
    const int acol  = (tid & 1) * 4;    // 0 or 4
    const int brow  = tid >> 5;         // 0..7
    const int bcol  = (tid & 31) * 4;   // 0..124

    const float* Aptr = A + (size_t)(row0 + arow) * K + acol;
    const float* Bptr = B + (size_t)brow * N + col0 + bcol;

    float acc[2][2][4][4];
#pragma unroll
    for (int i = 0; i < 2; i++)
#pragma unroll
        for (int j = 0; j < 2; j++)
#pragma unroll
            for (int r = 0; r < 4; r++)
#pragma unroll
                for (int c = 0; c < 4; c++)
                    acc[i][j][r][c] = 0.0f;

    for (int k0 = 0; k0 < K; k0 += 8) {
        float4 av = *(const float4*)Aptr;  Aptr += 8;
        float4 bv = *(const float4*)Bptr;  Bptr += (size_t)8 * N;

        As[acol + 0][arow] = av.x;
        As[acol + 1][arow] = av.y;
        As[acol + 2][arow] = av.z;
        As[acol + 3][arow] = av.w;
        *(float4*)&Bs[brow][bcol] = bv;
        __syncthreads();

#pragma unroll
        for (int k = 0; k < 8; k++) {
            float4 a0 = *(const float4*)&As[k][ty * 4];
            float4 a1 = *(const float4*)&As[k][64 + ty * 4];
            float4 b0 = *(const float4*)&Bs[k][tx * 4];
            float4 b1 = *(const float4*)&Bs[k][64 + tx * 4];
            float ar[8] = {a0.x, a0.y, a0.z, a0.w, a1.x, a1.y, a1.z, a1.w};
            float br[8] = {b0.x, b0.y, b0.z, b0.w, b1.x, b1.y, b1.z, b1.w};
#pragma unroll
            for (int ri = 0; ri < 2; ri++)
#pragma unroll
                for (int r = 0; r < 4; r++)
#pragma unroll
                    for (int ci = 0; ci < 2; ci++)
#pragma unroll
                        for (int c = 0; c < 4; c++)
                            acc[ri][ci][r][c] += ar[ri * 4 + r] * br[ci * 4 + c];
        }
        __syncthreads();
    }

#pragma unroll
    for (int ri = 0; ri < 2; ri++)
#pragma unroll
        for (int r = 0; r < 4; r++) {
            int row = row0 + ri * 64 + ty * 4 + r;
#pragma unroll
            for (int ci = 0; ci < 2; ci++) {
                int col = col0 + ci * 64 + tx * 4;
                float4 v = make_float4(acc[ri][ci][r][0], acc[ri][ci][r][1],
                                       acc[ri][ci][r][2], acc[ri][ci][r][3]);
                *(float4*)&C[(size_t)row * N + col] = v;
            }
        }
}

// ---------------------------------------------------------------------------
// Flash attention, fp32.
// grid = (SEQ/64, BATCH*HEADS); block = 256 threads (16x16).
// Q tile 64 queries; loop over 32 key tiles of 64.
// Smem rows padded to 65 floats -> conflict-free.
// Mask semantics: s = (q.k)*SCALE*mask[j], then standard softmax over ALL j
// (masked entries contribute exp(-m) -- they are NOT -inf).
// ---------------------------------------------------------------------------
#define ATTN_SMEM_FLOATS (3 * 64 * 65)
#define ATTN_SMEM_BYTES  (ATTN_SMEM_FLOATS * 4)

__global__ __launch_bounds__(256, 2)
void attn_kernel(const float* __restrict__ qkv, const float* __restrict__ mask,
                 float* __restrict__ outp)
{
    extern __shared__ float sm[];
    float* Qs  = sm;                 // [d][i] pad 65
    float* KPs = sm + 64 * 65;       // Ks: [d][j] pad 65; reused as Ps: [j][i] pad 65
    float* Vs  = sm + 2 * 64 * 65;   // [j][d] pad 65

    const int tid = threadIdx.x;
    const int tx  = tid & 15;        // key/feature group
    const int ty  = tid >> 4;        // query group
    const int bh  = blockIdx.y;
    const int b   = bh >> 4;
    const int h   = bh & 15;
    const int i0  = blockIdx.x * 64;

    const float* base = qkv + (size_t)b * SEQ * QKV_COLS;
    const float* qb = base + h * DHEAD;
    const float* kb = base + INNER + h * DHEAD;
    const float* vb = base + 2 * INNER + h * DHEAD;
    const float* mrow = mask + (size_t)b * SEQ;

    // Load Q transposed: Qs[d][i] = Q[i0+i][d]. Coalesced gmem; smem store
    // stride 64... wait: t-> i=t>>6, d=t&63 gives coalesced gmem (d contiguous)
    // and smem addr d*65+i: consecutive lanes differ by 65 -> conflict-free.
    for (int t = tid; t < 4096; t += 256) {
        int i = t >> 6, d = t & 63;
        Qs[d * 65 + i] = qb[(size_t)(i0 + i) * QKV_COLS + d];
    }

    float m_r[4], l_r[4], o[4][4];
#pragma unroll
    for (int r = 0; r < 4; r++) {
        m_r[r] = -1e30f;
        l_r[r] = 0.0f;
#pragma unroll
        for (int c = 0; c < 4; c++) o[r][c] = 0.0f;
    }
    __syncthreads();

    for (int j0 = 0; j0 < SEQ; j0 += 64) {
        // Load K (transposed [d][j]) and V ([j][d]).
        for (int t = tid; t < 4096; t += 256) {
            int j = t >> 6, d = t & 63;
            KPs[d * 65 + j] = kb[(size_t)(j0 + j) * QKV_COLS + d];
            Vs[j * 65 + d]  = vb[(size_t)(j0 + j) * QKV_COLS + d];
        }
        __syncthreads();

        // S = Q @ K^T  (this thread: rows ty*4.., cols tx*4..)
        float s[4][4];
#pragma unroll
        for (int r = 0; r < 4; r++)
#pragma unroll
            for (int c = 0; c < 4; c++) s[r][c] = 0.0f;

#pragma unroll 8
        for (int d = 0; d < 64; d++) {
            float a[4], bb[4];
#pragma unroll
            for (int r = 0; r < 4; r++) a[r] = Qs[d * 65 + ty * 4 + r];
#pragma unroll
            for (int c = 0; c < 4; c++) bb[c] = KPs[d * 65 + tx * 4 + c];
#pragma unroll
            for (int r = 0; r < 4; r++)
#pragma unroll
                for (int c = 0; c < 4; c++) s[r][c] += a[r] * bb[c];
        }

        // scale + multiplicative key mask
        float mk[4];
#pragma unroll
        for (int c = 0; c < 4; c++) mk[c] = mrow[j0 + tx * 4 + c] * ATT_SCALE;
#pragma unroll
        for (int r = 0; r < 4; r++)
#pragma unroll
            for (int c = 0; c < 4; c++) s[r][c] *= mk[c];

        // online softmax: row max across this thread's 4 cols, then across the
        // 16-lane (same ty) group. Lanes with equal ty occupy an aligned
        // 16-lane half-warp, so xor-shuffles 8/4/2/1 stay in-group.
        float p[4][4];
#pragma unroll
        for (int r = 0; r < 4; r++) {
            float rmax = fmaxf(fmaxf(s[r][0], s[r][1]), fmaxf(s[r][2], s[r][3]));
#pragma unroll
            for (int off = 8; off > 0; off >>= 1)
                rmax = fmaxf(rmax, __shfl_xor_sync(0xffffffffu, rmax, off));
            float mnew  = fmaxf(m_r[r], rmax);
            float alpha = __expf(m_r[r] - mnew);
            m_r[r] = mnew;
            l_r[r] *= alpha;
            float psum = 0.0f;
#pragma unroll
            for (int c = 0; c < 4; c++) {
                p[r][c] = __expf(s[r][c] - mnew);
                psum += p[r][c];
                o[r][c] *= alpha;
            }
            l_r[r] += psum;   // partial over this thread's cols; reduced at end
        }

        __syncthreads();   // everyone done reading Ks before P overwrites it
        // Ps[j][i] = p  (transposed for the PV pass)
#pragma unroll
        for (int c = 0; c < 4; c++)
#pragma unroll
            for (int r = 0; r < 4; r++)
                KPs[(tx * 4 + c) * 65 + ty * 4 + r] = p[r][c];
        __syncthreads();

        // O += P @ V  (this thread: rows ty*4.., d-cols tx*4..)
#pragma unroll 8
        for (int j = 0; j < 64; j++) {
            float a[4], v[4];
#pragma unroll
            for (int r = 0; r < 4; r++) a[r] = KPs[j * 65 + ty * 4 + r];
#pragma unroll
            for (int c = 0; c < 4; c++) v[c] = Vs[j * 65 + tx * 4 + c];
#pragma unroll
            for (int r = 0; r < 4; r++)
#pragma unroll
                for (int c = 0; c < 4; c++) o[r][c] += a[r] * v[c];
        }
        __syncthreads();   // before next tile's loads overwrite Ks/Vs
    }

    // finalize: reduce l across the 16-lane group, normalize, write out
#pragma unroll
    for (int r = 0; r < 4; r++) {
#pragma unroll
        for (int off = 8; off > 0; off >>= 1)
            l_r[r] += __shfl_xor_sync(0xffffffffu, l_r[r], off);
        float inv = 1.0f / l_r[r];
        int row = i0 + ty * 4 + r;
        float* op = outp + (size_t)b * SEQ * INNER + (size_t)row * INNER
                    + h * DHEAD + tx * 4;
#pragma unroll
        for (int c = 0; c < 4; c++) op[c] = o[r][c] * inv;
    }
}

// ---------------------------------------------------------------------------
// Launch
// ---------------------------------------------------------------------------
extern "C" void kernel_launch(void* const* d_in, const int* in_sizes, int n_in,
                              void* d_out, int out_size)
{
    const float* x     = (const float*)d_in[0];   // [2,2048,1024]
    const float* smask = (const float*)d_in[1];   // [2,2048]
    const float* wqkv  = (const float*)d_in[2];   // [1024,3072]
    const float* wout  = (const float*)d_in[3];   // [1024,1024]
    float* out = (float*)d_out;                   // [2,2048,1024]

    float *qkvp = nullptr, *attp = nullptr;
    cudaGetSymbolAddress((void**)&qkvp, g_qkv);
    cudaGetSymbolAddress((void**)&attp, g_att);

    cudaFuncSetAttribute(attn_kernel, cudaFuncAttributeMaxDynamicSharedMemorySize,
                         ATTN_SMEM_BYTES);

    // 1) qkv = x @ w_qkv   : [4096,1024]x[1024,3072]
    sgemm_kernel<<<dim3(QKV_COLS / 128, MROWS / 128), 256>>>(
        x, wqkv, qkvp, MROWS, QKV_COLS, DIM);

    // 2) flash attention -> g_att [b, n, h*64+d]
    attn_kernel<<<dim3(SEQ / 64, BATCH * HEADS), 256, ATTN_SMEM_BYTES>>>(
        qkvp, smask, attp);

    // 3) out = g_att @ w_out : [4096,1024]x[1024,1024]
    sgemm_kernel<<<dim3(DIM / 128, MROWS / 128), 256>>>(
        attp, wout, out, MROWS, DIM, DIM);
}

// round 2
// speedup vs baseline: 1.1288x; 1.1288x over previous
#include <cuda_runtime.h>
#include <cuda_bf16.h>
#include <math.h>

// Problem constants
#define BATCH 2
#define SEQ   2048
#define DIM   1024
#define HEADS 16
#define DHEAD 64
#define INNER 1024              // HEADS*DHEAD
#define QKV_COLS 3072           // 3*INNER
#define MROWS 4096              // BATCH*SEQ
#define ATT_SCALE 0.125f        // 64^-0.5

// Scratch (device globals — no cudaMalloc allowed)
__device__ float g_qkv[(size_t)BATCH * SEQ * QKV_COLS];   // 50.3 MB
__device__ float g_att[(size_t)BATCH * SEQ * INNER];      // 16.8 MB

// Packed f32x2 FMA: d = a*b + c (per-lane pair). rt_SMSP=2 but 2 FMA/instr ->
// 2x throughput vs scalar 3-reg FFMA (which is RF-bank-limited to rt=2).
__device__ __forceinline__ float2 ffma2(float2 a, float2 b, float2 c) {
    float2 d;
    asm("{\n\t"
        ".reg .b64 ra, rb, rc, rd;\n\t"
        "mov.b64 ra, {%2, %3};\n\t"
        "mov.b64 rb, {%4, %5};\n\t"
        "mov.b64 rc, {%6, %7};\n\t"
        "fma.rn.f32x2 rd, ra, rb, rc;\n\t"
        "mov.b64 {%0, %1}, rd;\n\t"
        "}"
        : "=f"(d.x), "=f"(d.y)
        : "f"(a.x), "f"(a.y), "f"(b.x), "f"(b.y), "f"(c.x), "f"(c.y));
    return d;
}

// ---------------------------------------------------------------------------
// SGEMM: C[M,N] = A[M,K] @ B[K,N], row-major fp32, FFMA2 inner loop.
// 128x128 block tile, BK=8, 256 threads, 8x8 per thread (2x2 quadrants).
// Register-prefetch pipeline over the k-chunks.
// ---------------------------------------------------------------------------
__global__ __launch_bounds__(256, 2)
void sgemm_kernel(const float* __restrict__ A, const float* __restrict__ B,
                  float* __restrict__ C, int M, int N, int K)
{
    __shared__ float As[8][128];   // transposed: As[k][m]
    __shared__ float Bs[8][128];   // Bs[k][n]

    const int tid = threadIdx.x;
    const int tx  = tid & 15;      // 0..15
    const int ty  = tid >> 4;      // 0..15
    const int row0 = blockIdx.y * 128;
    const int col0 = blockIdx.x * 128;

    const int arow  = tid >> 1;         // 0..127
    const int acol  = (tid & 1) * 4;    // 0 or 4
    const int brow  = tid >> 5;         // 0..7
    const int bcol  = (tid & 31) * 4;   // 0..124

    const float* Aptr = A + (size_t)(row0 + arow) * K + acol;
    const float* Bptr = B + (size_t)brow * N + col0 + bcol;

    float2 acc[8][4];                   // 8 rows x 8 cols (4 pairs)
#pragma unroll
    for (int r = 0; r < 8; r++)
#pragma unroll
        for (int c = 0; c < 4; c++) acc[r][c] = make_float2(0.f, 0.f);

    float4 av = *(const float4*)Aptr;
    float4 bv = *(const float4*)Bptr;

    for (int k0 = 0; k0 < K; k0 += 8) {
        As[acol + 0][arow] = av.x;
        As[acol + 1][arow] = av.y;
        As[acol + 2][arow] = av.z;
        As[acol + 3][arow] = av.w;
        *(float4*)&Bs[brow][bcol] = bv;
        __syncthreads();

        Aptr += 8;
        Bptr += (size_t)8 * N;
        if (k0 + 8 < K) {               // prefetch next chunk during compute
            av = *(const float4*)Aptr;
            bv = *(const float4*)Bptr;
        }

#pragma unroll
        for (int k = 0; k < 8; k++) {
            float4 a0 = *(const float4*)&As[k][ty * 4];
            float4 a1 = *(const float4*)&As[k][64 + ty * 4];
            float4 b0 = *(const float4*)&Bs[k][tx * 4];
            float4 b1 = *(const float4*)&Bs[k][64 + tx * 4];
            float  ar[8] = {a0.x, a0.y, a0.z, a0.w, a1.x, a1.y, a1.z, a1.w};
            float2 bp[4] = {{b0.x, b0.y}, {b0.z, b0.w},
                            {b1.x, b1.y}, {b1.z, b1.w}};
#pragma unroll
            for (int r = 0; r < 8; r++) {
                float2 ad = make_float2(ar[r], ar[r]);
#pragma unroll
                for (int c = 0; c < 4; c++)
                    acc[r][c] = ffma2(ad, bp[c], acc[r][c]);
            }
        }
        __syncthreads();
    }

#pragma unroll
    for (int r = 0; r < 8; r++) {
        int row = row0 + (r >> 2) * 64 + ty * 4 + (r & 3);
        float4 v0 = make_float4(acc[r][0].x, acc[r][0].y, acc[r][1].x, acc[r][1].y);
        float4 v1 = make_float4(acc[r][2].x, acc[r][2].y, acc[r][3].x, acc[r][3].y);
        *(float4*)&C[(size_t)row * N + col0 + tx * 4] = v0;
        *(float4*)&C[(size_t)row * N + col0 + 64 + tx * 4] = v1;
    }
}

// ---------------------------------------------------------------------------
// Flash attention, fp32, FFMA2, 128x128 S-tile, 8x8 per thread.
// grid = (SEQ/128, BATCH*HEADS); block = 256 threads (16x16).
// Mask semantics: s = (q.k)*SCALE*mask[j], softmax over ALL j (not -inf).
// Smem (floats): Qs[64][129], Ks[64][129], Vs[128][65], Ps[128][129].
// ---------------------------------------------------------------------------
#define QS_OFF  0
#define KS_OFF  (64 * 129)
#define VS_OFF  (KS_OFF + 64 * 129)
#define PS_OFF  (VS_OFF + 128 * 65)
#define ATTN_SMEM_FLOATS (PS_OFF + 128 * 129)
#define ATTN_SMEM_BYTES  (ATTN_SMEM_FLOATS * 4)

__global__ __launch_bounds__(256, 1)
void attn_kernel(const float* __restrict__ qkv, const float* __restrict__ mask,
                 float* __restrict__ outp)
{
    extern __shared__ float sm[];
    float* Qs = sm + QS_OFF;    // [d][i]  stride 129
    float* Ks = sm + KS_OFF;    // [d][j]  stride 129
    float* Vs = sm + VS_OFF;    // [j][d]  stride 65
    float* Ps = sm + PS_OFF;    // [j][i]  stride 129

    const int tid = threadIdx.x;
    const int tx  = tid & 15;
    const int ty  = tid >> 4;
    const int bh  = blockIdx.y;
    const int b   = bh >> 4;
    const int h   = bh & 15;
    const int i0  = blockIdx.x * 128;

    const float* base = qkv + (size_t)b * SEQ * QKV_COLS;
    const float* qb = base + h * DHEAD;
    const float* kb = base + INNER + h * DHEAD;
    const float* vb = base + 2 * INNER + h * DHEAD;
    const float* mrow = mask + (size_t)b * SEQ;

    // Load Q transposed: Qs[d][i]. Consecutive tids -> consecutive d (gmem
    // coalesced); smem store stride 129 per lane -> conflict-free.
    for (int t = tid; t < 128 * 64; t += 256) {
        int i = t >> 6, d = t & 63;
        Qs[d * 129 + i] = qb[(size_t)(i0 + i) * QKV_COLS + d];
    }

    float  m_r[8], l_r[8];
    float2 o[8][2];                 // 8 rows x 4 d-cols (2 pairs)
#pragma unroll
    for (int r = 0; r < 8; r++) {
        m_r[r] = -1e30f;
        l_r[r] = 0.0f;
        o[r][0] = make_float2(0.f, 0.f);
        o[r][1] = make_float2(0.f, 0.f);
    }
    __syncthreads();

    for (int j0 = 0; j0 < SEQ; j0 += 128) {
        // Load K (transposed [d][j]) and V ([j][d])
        for (int t = tid; t < 128 * 64; t += 256) {
            int j = t >> 6, d = t & 63;
            Ks[d * 129 + j] = kb[(size_t)(j0 + j) * QKV_COLS + d];
            Vs[j * 65 + d]  = vb[(size_t)(j0 + j) * QKV_COLS + d];
        }
        __syncthreads();

        // S = Q @ K^T : rows {ty*4..+3, 64+ty*4..+3}, cols {tx*4..+3, 64+tx*4..+3}
        float2 s[8][4];
#pragma unroll
        for (int r = 0; r < 8; r++)
#pragma unroll
            for (int c = 0; c < 4; c++) s[r][c] = make_float2(0.f, 0.f);

        {
            const float* qp = Qs + ty * 4;
            const float* kp = Ks + tx * 4;
#pragma unroll 4
            for (int d = 0; d < 64; d++) {
                const float* qr = qp + d * 129;
                const float* kr = kp + d * 129;
                float a[8] = {qr[0], qr[1], qr[2], qr[3],
                              qr[64], qr[65], qr[66], qr[67]};
                float2 bp[4] = {{kr[0], kr[1]}, {kr[2], kr[3]},
                                {kr[64], kr[65]}, {kr[66], kr[67]}};
#pragma unroll
                for (int r = 0; r < 8; r++) {
                    float2 ad = make_float2(a[r], a[r]);
#pragma unroll
                    for (int c = 0; c < 4; c++)
                        s[r][c] = ffma2(ad, bp[c], s[r][c]);
                }
            }
        }

        // scale + multiplicative key mask (per key column)
        float2 mk[4];
#pragma unroll
        for (int c2 = 0; c2 < 4; c2++) {
            int colj = (c2 >> 1) * 64 + tx * 4 + (c2 & 1) * 2;
            mk[c2].x = mrow[j0 + colj] * ATT_SCALE;
            mk[c2].y = mrow[j0 + colj + 1] * ATT_SCALE;
        }
#pragma unroll
        for (int r = 0; r < 8; r++)
#pragma unroll
            for (int c = 0; c < 4; c++) {
                s[r][c].x *= mk[c].x;
                s[r][c].y *= mk[c].y;
            }

        // online softmax per row (16-lane groups share a row; aligned halves
        // of a warp so xor-shuffles 8/4/2/1 stay in-group)
#pragma unroll
        for (int r = 0; r < 8; r++) {
            float rmax = s[r][0].x;
#pragma unroll
            for (int c = 0; c < 4; c++) {
                rmax = fmaxf(rmax, s[r][c].x);
                rmax = fmaxf(rmax, s[r][c].y);
            }
#pragma unroll
            for (int off = 8; off > 0; off >>= 1)
                rmax = fmaxf(rmax, __shfl_xor_sync(0xffffffffu, rmax, off));
            float mnew  = fmaxf(m_r[r], rmax);
            float alpha = __expf(m_r[r] - mnew);
            m_r[r] = mnew;
            l_r[r] *= alpha;
            o[r][0].x *= alpha; o[r][0].y *= alpha;
            o[r][1].x *= alpha; o[r][1].y *= alpha;
            float psum = 0.0f;
#pragma unroll
            for (int c = 0; c < 4; c++) {
                s[r][c].x = __expf(s[r][c].x - mnew);
                s[r][c].y = __expf(s[r][c].y - mnew);
                psum += s[r][c].x + s[r][c].y;
            }
            l_r[r] += psum;     // partial over this thread's cols; reduced at end
        }

        __syncthreads();   // prev PV done reading Ps (and Ks free)
        // Ps[j][i] = p (transposed for PV)
#pragma unroll
        for (int c2 = 0; c2 < 4; c2++) {
            int colj = (c2 >> 1) * 64 + tx * 4 + (c2 & 1) * 2;
#pragma unroll
            for (int r = 0; r < 8; r++) {
                int rowi = (r >> 2) * 64 + ty * 4 + (r & 3);
                Ps[colj * 129 + rowi]       = s[r][c2].x;
                Ps[(colj + 1) * 129 + rowi] = s[r][c2].y;
            }
        }
        __syncthreads();

        // O += P @ V : rows as above, d-cols tx*4..+3
        {
            const float* pp = Ps + ty * 4;
            const float* vp = Vs + tx * 4;
#pragma unroll 4
            for (int j = 0; j < 128; j++) {
                const float* pr = pp + j * 129;
                const float* vr = vp + j * 65;
                float a[8] = {pr[0], pr[1], pr[2], pr[3],
                              pr[64], pr[65], pr[66], pr[67]};
                float2 vv[2] = {{vr[0], vr[1]}, {vr[2], vr[3]}};
#pragma unroll
                for (int r = 0; r < 8; r++) {
                    float2 ad = make_float2(a[r], a[r]);
                    o[r][0] = ffma2(ad, vv[0], o[r][0]);
                    o[r][1] = ffma2(ad, vv[1], o[r][1]);
                }
            }
        }
        __syncthreads();   // before next tile's loads overwrite Ks/Vs/Ps
    }

    // finalize: reduce l across the 16-lane group, normalize, write out
#pragma unroll
    for (int r = 0; r < 8; r++) {
        float l = l_r[r];
#pragma unroll
        for (int off = 8; off > 0; off >>= 1)
            l += __shfl_xor_sync(0xffffffffu, l, off);
        float inv = 1.0f / l;
        int row = i0 + (r >> 2) * 64 + ty * 4 + (r & 3);
        float4 v = make_float4(o[r][0].x * inv, o[r][0].y * inv,
                               o[r][1].x * inv, o[r][1].y * inv);
        *(float4*)&outp[(size_t)b * SEQ * INNER + (size_t)row * INNER
                        + h * DHEAD + tx * 4] = v;
    }
}

// ---------------------------------------------------------------------------
// Launch
// ---------------------------------------------------------------------------
extern "C" void kernel_launch(void* const* d_in, const int* in_sizes, int n_in,
                              void* d_out, int out_size)
{
    const float* x     = (const float*)d_in[0];   // [2,2048,1024]
    const float* smask = (const float*)d_in[1];   // [2,2048]
    const float* wqkv  = (const float*)d_in[2];   // [1024,3072]
    const float* wout  = (const float*)d_in[3];   // [1024,1024]
    float* out = (float*)d_out;                   // [2,2048,1024]

    float *qkvp = nullptr, *attp = nullptr;
    cudaGetSymbolAddress((void**)&qkvp, g_qkv);
    cudaGetSymbolAddress((void**)&attp, g_att);

    cudaFuncSetAttribute(attn_kernel, cudaFuncAttributeMaxDynamicSharedMemorySize,
                         ATTN_SMEM_BYTES);

    // 1) qkv = x @ w_qkv   : [4096,1024]x[1024,3072]
    sgemm_kernel<<<dim3(QKV_COLS / 128, MROWS / 128), 256>>>(
        x, wqkv, qkvp, MROWS, QKV_COLS, DIM);

    // 2) flash attention -> g_att
    attn_kernel<<<dim3(SEQ / 128, BATCH * HEADS), 256, ATTN_SMEM_BYTES>>>(
        qkvp, smask, attp);

    // 3) out = g_att @ w_out : [4096,1024]x[1024,1024]
    sgemm_kernel<<<dim3(DIM / 128, MROWS / 128), 256>>>(
        attp, wout, out, MROWS, DIM, DIM);
}

// round 4
// speedup vs baseline: 1.3671x; 1.2111x over previous
#include <cuda_runtime.h>
#include <cuda_bf16.h>
#include <cstdint>
#include <math.h>

// Problem constants
#define BATCH 2
#define SEQ   2048
#define DIM   1024
#define HEADS 16
#define DHEAD 64
#define INNER 1024
#define QKV_COLS 3072
#define MROWS 4096              // BATCH*SEQ
#define KP    3072              // split-K': 3*1024
#define ATT_SCALE 0.125f

// Scratch (device globals — no cudaMalloc allowed)
__device__ float g_qkv[(size_t)BATCH * SEQ * QKV_COLS];       // 50.3 MB
__device__ float g_att[(size_t)BATCH * SEQ * INNER];          // 16.8 MB
__device__ __nv_bfloat16 g_Aq [(size_t)MROWS * KP];           // [hi|hi|lo]
__device__ __nv_bfloat16 g_Wq [(size_t)QKV_COLS * KP];        // [hi|lo|hi] (transposed)
__device__ __nv_bfloat16 g_Wo [(size_t)DIM * KP];
__device__ __nv_bfloat16 g_A2q[(size_t)MROWS * KP];

// ---------------------------------------------------------------------------
// PTX helpers (all plain sm_80+-compatible — no tcgen05: harness lowers via
// virtual arch compute_103, which rejects arch-accelerated instructions)
// ---------------------------------------------------------------------------
__device__ __forceinline__ uint32_t smem_u32(const void* p) {
    uint32_t a;
    asm("{ .reg .u64 t; cvta.to.shared.u64 t, %1; cvt.u32.u64 %0, t; }"
        : "=r"(a) : "l"(p));
    return a;
}
#define SWZ128(o) ((o) ^ (((o) >> 3) & 0x70))
#define CP16(dst, src)  asm volatile("cp.async.cg.shared.global [%0], [%1], 16;" :: "r"(dst), "l"(src) : "memory")
#define CP_COMMIT()     asm volatile("cp.async.commit_group;" ::: "memory")
#define CP_WAIT1()      asm volatile("cp.async.wait_group 1;" ::: "memory")

#define LDSM4(r0, r1, r2, r3, addr) \
    asm volatile("ldmatrix.sync.aligned.m8n8.x4.shared.b16 {%0,%1,%2,%3}, [%4];" \
                 : "=r"(r0), "=r"(r1), "=r"(r2), "=r"(r3) : "r"(addr))

#define MMA16816(d, a, b0, b1) \
    asm volatile("mma.sync.aligned.m16n8k16.row.col.f32.bf16.bf16.f32 " \
                 "{%0,%1,%2,%3}, {%4,%5,%6,%7}, {%8,%9}, {%0,%1,%2,%3};" \
                 : "+f"((d)[0]), "+f"((d)[1]), "+f"((d)[2]), "+f"((d)[3]) \
                 : "r"((a)[0]), "r"((a)[1]), "r"((a)[2]), "r"((a)[3]), \
                   "r"(b0), "r"(b1))

// Packed f32x2 FMA (attention kernel)
__device__ __forceinline__ float2 ffma2(float2 a, float2 b, float2 c) {
    float2 d;
    asm("{\n\t.reg .b64 ra, rb, rc, rd;\n\t"
        "mov.b64 ra, {%2, %3};\n\tmov.b64 rb, {%4, %5};\n\tmov.b64 rc, {%6, %7};\n\t"
        "fma.rn.f32x2 rd, ra, rb, rc;\n\tmov.b64 {%0, %1}, rd;\n\t}"
        : "=f"(d.x), "=f"(d.y)
        : "f"(a.x), "f"(a.y), "f"(b.x), "f"(b.y), "f"(c.x), "f"(c.y));
    return d;
}

// ---------------------------------------------------------------------------
// Split/convert kernels (fp32 -> bf16 hi/lo, K-concat layout)
// ---------------------------------------------------------------------------
__global__ void split_a_kernel(const float* __restrict__ in,
                               __nv_bfloat16* __restrict__ out, int rows)
{
    int idx = blockIdx.x * 256 + threadIdx.x;
    if (idx >= rows * 1024) return;
    int m = idx >> 10, k = idx & 1023;
    float v = in[idx];
    __nv_bfloat16 hi = __float2bfloat16(v);
    __nv_bfloat16 lo = __float2bfloat16(v - __bfloat162float(hi));
    size_t o = (size_t)m * KP + k;
    out[o] = hi; out[o + 1024] = hi; out[o + 2048] = lo;
}

// Weights [1024 x N] -> transposed [N x 3072] = [hi | lo | hi]
__global__ void split_w_kernel(const float* __restrict__ w,
                               __nv_bfloat16* __restrict__ out, int N)
{
    __shared__ float t[32][33];
    int bk = blockIdx.y * 32, bn = blockIdx.x * 32;
    int tx = threadIdx.x, ty = threadIdx.y;   // (32, 8)
#pragma unroll
    for (int i = 0; i < 4; i++)
        t[ty + 8 * i][tx] = w[(size_t)(bk + ty + 8 * i) * N + bn + tx];
    __syncthreads();
#pragma unroll
    for (int i = 0; i < 4; i++) {
        int n = bn + ty + 8 * i, k = bk + tx;
        float v = t[tx][ty + 8 * i];
        __nv_bfloat16 hi = __float2bfloat16(v);
        __nv_bfloat16 lo = __float2bfloat16(v - __bfloat162float(hi));
        size_t o = (size_t)n * KP + k;
        out[o] = hi; out[o + 1024] = lo; out[o + 2048] = hi;
    }
}

// ---------------------------------------------------------------------------
// bf16 GEMM via mma.sync: C[M,N] = A'[M,KP] @ B'[N,KP]^T, fp32 accumulate.
// 128x128 CTA tile, BK=64, 3-stage cp.async pipeline, 256 threads (8 warps
// as 4x2: warp tile 32m x 64n = 2x8 m16n8k16 per k-step).
// SMEM per stage: A 128x64 bf16 (16KB, SW128 rows of 128B) + B same.
// ---------------------------------------------------------------------------
#define GSTAGES 3
#define STAGE_BYTES 32768
#define GSMEM_BYTES (GSTAGES * STAGE_BYTES)
#define NCHUNK (KP / 64)     // 48

__device__ __forceinline__ void gemm_load_chunk(
    uint32_t sb, int stage, int chunk, int tid,
    const __nv_bfloat16* __restrict__ A, const __nv_bfloat16* __restrict__ B,
    int row0, int col0)
{
    uint32_t sA = sb + stage * STAGE_BYTES;
    uint32_t sB = sA + 16384;
    int k0 = chunk * 64;
#pragma unroll
    for (int i = 0; i < 4; i++) {
        int g = tid + i * 256;          // 0..1023
        int row = g >> 3, c16 = g & 7;  // 128 rows x 8 16B-granules
        uint32_t off = SWZ128((uint32_t)(row * 128 + c16 * 16));
        CP16(sA + off, A + (size_t)(row0 + row) * KP + k0 + c16 * 8);
        CP16(sB + off, B + (size_t)(col0 + row) * KP + k0 + c16 * 8);
    }
}

__global__ __launch_bounds__(256, 2)
void mma_gemm_kernel(const __nv_bfloat16* __restrict__ A,
                     const __nv_bfloat16* __restrict__ B,
                     float* __restrict__ C, int N)
{
    extern __shared__ char smem[];
    uint32_t sb = smem_u32(smem);
    const int tid  = threadIdx.x;
    const int lane = tid & 31;
    const int wid  = tid >> 5;
    const int wm   = wid & 3;        // warp m: 4 x 32 rows
    const int wn   = wid >> 2;       // warp n: 2 x 64 cols
    const int row0 = blockIdx.y * 128;
    const int col0 = blockIdx.x * 128;

    float acc[2][8][4];
#pragma unroll
    for (int mt = 0; mt < 2; mt++)
#pragma unroll
        for (int nt = 0; nt < 8; nt++)
#pragma unroll
            for (int v = 0; v < 4; v++) acc[mt][nt][v] = 0.0f;

    // prologue: chunks 0,1
    gemm_load_chunk(sb, 0, 0, tid, A, B, row0, col0);
    CP_COMMIT();
    gemm_load_chunk(sb, 1, 1, tid, A, B, row0, col0);
    CP_COMMIT();

    // per-lane ldmatrix address components (within tile, before swizzle)
    const int arow_l = wm * 32 + (lane & 15);   // + mt*16
    const int brow_l = wn * 64 + (lane & 15);   // + np*16
    const int khalf  = (lane >> 4) * 16;        // byte offset of k-half

    for (int c = 0; c < NCHUNK; c++) {
        CP_WAIT1();                 // chunk c resident (chunk c+1 may be in flight)
        __syncthreads();            // all warps done with stage (c-1)%3 reads

        int nc = c + 2;
        if (nc < NCHUNK)
            gemm_load_chunk(sb, nc % 3, nc, tid, A, B, row0, col0);
        CP_COMMIT();                // one group per iter (possibly empty)

        uint32_t sA = sb + (c % 3) * STAGE_BYTES;
        uint32_t sB = sA + 16384;

#pragma unroll
        for (int ks = 0; ks < 4; ks++) {
            const int kb = ks * 32 + khalf;
            uint32_t a[2][4], b[4][4];
#pragma unroll
            for (int mt = 0; mt < 2; mt++) {
                uint32_t ad = sA + SWZ128((uint32_t)((arow_l + mt * 16) * 128 + kb));
                LDSM4(a[mt][0], a[mt][1], a[mt][2], a[mt][3], ad);
            }
#pragma unroll
            for (int np = 0; np < 4; np++) {
                uint32_t bd = sB + SWZ128((uint32_t)((brow_l + np * 16) * 128 + kb));
                LDSM4(b[np][0], b[np][1], b[np][2], b[np][3], bd);
            }
#pragma unroll
            for (int mt = 0; mt < 2; mt++)
#pragma unroll
                for (int nt = 0; nt < 8; nt++) {
                    int np = nt >> 1, sel = nt & 1;
                    MMA16816(acc[mt][nt], a[mt], b[np][sel], b[np][2 + sel]);
                }
        }
    }

    // epilogue: write C (fragment layout: g=lane>>2 row, t=lane&3 col pair)
    const int g = lane >> 2, t = lane & 3;
#pragma unroll
    for (int mt = 0; mt < 2; mt++) {
        int row = row0 + wm * 32 + mt * 16 + g;
#pragma unroll
        for (int nt = 0; nt < 8; nt++) {
            int col = col0 + wn * 64 + nt * 8 + t * 2;
            *(float2*)&C[(size_t)row * N + col] =
                make_float2(acc[mt][nt][0], acc[mt][nt][1]);
            *(float2*)&C[(size_t)(row + 8) * N + col] =
                make_float2(acc[mt][nt][2], acc[mt][nt][3]);
        }
    }
}

// ---------------------------------------------------------------------------
// Flash attention, fp32, FFMA2, 128x128 S-tile, 8x8 per thread (unchanged).
// ---------------------------------------------------------------------------
#define QS_OFF  0
#define KS_OFF  (64 * 129)
#define VS_OFF  (KS_OFF + 64 * 129)
#define PS_OFF  (VS_OFF + 128 * 65)
#define ATTN_SMEM_FLOATS (PS_OFF + 128 * 129)
#define ATTN_SMEM_BYTES  (ATTN_SMEM_FLOATS * 4)

__global__ __launch_bounds__(256, 1)
void attn_kernel(const float* __restrict__ qkv, const float* __restrict__ mask,
                 float* __restrict__ outp)
{
    extern __shared__ float sm[];
    float* Qs = sm + QS_OFF;    // [d][i]  stride 129
    float* Ks = sm + KS_OFF;    // [d][j]  stride 129
    float* Vs = sm + VS_OFF;    // [j][d]  stride 65
    float* Ps = sm + PS_OFF;    // [j][i]  stride 129

    const int tid = threadIdx.x;
    const int tx  = tid & 15;
    const int ty  = tid >> 4;
    const int bh  = blockIdx.y;
    const int b   = bh >> 4;
    const int h   = bh & 15;
    const int i0  = blockIdx.x * 128;

    const float* base = qkv + (size_t)b * SEQ * QKV_COLS;
    const float* qb = base + h * DHEAD;
    const float* kb = base + INNER + h * DHEAD;
    const float* vb = base + 2 * INNER + h * DHEAD;
    const float* mrow = mask + (size_t)b * SEQ;

    for (int t = tid; t < 128 * 64; t += 256) {
        int i = t >> 6, d = t & 63;
        Qs[d * 129 + i] = qb[(size_t)(i0 + i) * QKV_COLS + d];
    }

    float  m_r[8], l_r[8];
    float2 o[8][2];
#pragma unroll
    for (int r = 0; r < 8; r++) {
        m_r[r] = -1e30f; l_r[r] = 0.0f;
        o[r][0] = make_float2(0.f, 0.f);
        o[r][1] = make_float2(0.f, 0.f);
    }
    __syncthreads();

    for (int j0 = 0; j0 < SEQ; j0 += 128) {
        for (int t = tid; t < 128 * 64; t += 256) {
            int j = t >> 6, d = t & 63;
            Ks[d * 129 + j] = kb[(size_t)(j0 + j) * QKV_COLS + d];
            Vs[j * 65 + d]  = vb[(size_t)(j0 + j) * QKV_COLS + d];
        }
        __syncthreads();

        float2 s[8][4];
#pragma unroll
        for (int r = 0; r < 8; r++)
#pragma unroll
            for (int c = 0; c < 4; c++) s[r][c] = make_float2(0.f, 0.f);

        {
            const float* qp = Qs + ty * 4;
            const float* kp = Ks + tx * 4;
#pragma unroll 4
            for (int d = 0; d < 64; d++) {
                const float* qr = qp + d * 129;
                const float* kr = kp + d * 129;
                float a[8] = {qr[0], qr[1], qr[2], qr[3],
                              qr[64], qr[65], qr[66], qr[67]};
                float2 bp[4] = {{kr[0], kr[1]}, {kr[2], kr[3]},
                                {kr[64], kr[65]}, {kr[66], kr[67]}};
#pragma unroll
                for (int r = 0; r < 8; r++) {
                    float2 ad = make_float2(a[r], a[r]);
#pragma unroll
                    for (int c = 0; c < 4; c++)
                        s[r][c] = ffma2(ad, bp[c], s[r][c]);
                }
            }
        }

        float2 mk[4];
#pragma unroll
        for (int c2 = 0; c2 < 4; c2++) {
            int colj = (c2 >> 1) * 64 + tx * 4 + (c2 & 1) * 2;
            mk[c2].x = mrow[j0 + colj] * ATT_SCALE;
            mk[c2].y = mrow[j0 + colj + 1] * ATT_SCALE;
        }
#pragma unroll
        for (int r = 0; r < 8; r++)
#pragma unroll
            for (int c = 0; c < 4; c++) {
                s[r][c].x *= mk[c].x;
                s[r][c].y *= mk[c].y;
            }

#pragma unroll
        for (int r = 0; r < 8; r++) {
            float rmax = s[r][0].x;
#pragma unroll
            for (int c = 0; c < 4; c++) {
                rmax = fmaxf(rmax, s[r][c].x);
                rmax = fmaxf(rmax, s[r][c].y);
            }
#pragma unroll
            for (int off = 8; off > 0; off >>= 1)
                rmax = fmaxf(rmax, __shfl_xor_sync(0xffffffffu, rmax, off));
            float mnew  = fmaxf(m_r[r], rmax);
            float alpha = __expf(m_r[r] - mnew);
            m_r[r] = mnew;
            l_r[r] *= alpha;
            o[r][0].x *= alpha; o[r][0].y *= alpha;
            o[r][1].x *= alpha; o[r][1].y *= alpha;
            float psum = 0.0f;
#pragma unroll
            for (int c = 0; c < 4; c++) {
                s[r][c].x = __expf(s[r][c].x - mnew);
                s[r][c].y = __expf(s[r][c].y - mnew);
                psum += s[r][c].x + s[r][c].y;
            }
            l_r[r] += psum;
        }

        __syncthreads();
#pragma unroll
        for (int c2 = 0; c2 < 4; c2++) {
            int colj = (c2 >> 1) * 64 + tx * 4 + (c2 & 1) * 2;
#pragma unroll
            for (int r = 0; r < 8; r++) {
                int rowi = (r >> 2) * 64 + ty * 4 + (r & 3);
                Ps[colj * 129 + rowi]       = s[r][c2].x;
                Ps[(colj + 1) * 129 + rowi] = s[r][c2].y;
            }
        }
        __syncthreads();

        {
            const float* pp = Ps + ty * 4;
            const float* vp = Vs + tx * 4;
#pragma unroll 4
            for (int j = 0; j < 128; j++) {
                const float* pr = pp + j * 129;
                const float* vr = vp + j * 65;
                float a[8] = {pr[0], pr[1], pr[2], pr[3],
                              pr[64], pr[65], pr[66], pr[67]};
                float2 vv[2] = {{vr[0], vr[1]}, {vr[2], vr[3]}};
#pragma unroll
                for (int r = 0; r < 8; r++) {
                    float2 ad = make_float2(a[r], a[r]);
                    o[r][0] = ffma2(ad, vv[0], o[r][0]);
                    o[r][1] = ffma2(ad, vv[1], o[r][1]);
                }
            }
        }
        __syncthreads();
    }

#pragma unroll
    for (int r = 0; r < 8; r++) {
        float l = l_r[r];
#pragma unroll
        for (int off = 8; off > 0; off >>= 1)
            l += __shfl_xor_sync(0xffffffffu, l, off);
        float inv = 1.0f / l;
        int row = i0 + (r >> 2) * 64 + ty * 4 + (r & 3);
        float4 v = make_float4(o[r][0].x * inv, o[r][0].y * inv,
                               o[r][1].x * inv, o[r][1].y * inv);
        *(float4*)&outp[(size_t)b * SEQ * INNER + (size_t)row * INNER
                        + h * DHEAD + tx * 4] = v;
    }
}

// ---------------------------------------------------------------------------
// Launch
// ---------------------------------------------------------------------------
extern "C" void kernel_launch(void* const* d_in, const int* in_sizes, int n_in,
                              void* d_out, int out_size)
{
    const float* x     = (const float*)d_in[0];
    const float* smask = (const float*)d_in[1];
    const float* wqkv  = (const float*)d_in[2];   // [1024,3072]
    const float* wout  = (const float*)d_in[3];   // [1024,1024]
    float* out = (float*)d_out;

    float *qkvp, *attp;
    __nv_bfloat16 *aq, *wq, *wo, *a2q;
    cudaGetSymbolAddress((void**)&qkvp, g_qkv);
    cudaGetSymbolAddress((void**)&attp, g_att);
    cudaGetSymbolAddress((void**)&aq,  g_Aq);
    cudaGetSymbolAddress((void**)&wq,  g_Wq);
    cudaGetSymbolAddress((void**)&wo,  g_Wo);
    cudaGetSymbolAddress((void**)&a2q, g_A2q);

    cudaFuncSetAttribute(attn_kernel, cudaFuncAttributeMaxDynamicSharedMemorySize,
                         ATTN_SMEM_BYTES);
    cudaFuncSetAttribute(mma_gemm_kernel, cudaFuncAttributeMaxDynamicSharedMemorySize,
                         GSMEM_BYTES);

    // 0) split/convert inputs
    split_a_kernel<<<MROWS * 1024 / 256, 256>>>(x, aq, MROWS);
    split_w_kernel<<<dim3(QKV_COLS / 32, 32), dim3(32, 8)>>>(wqkv, wq, QKV_COLS);
    split_w_kernel<<<dim3(DIM / 32, 32), dim3(32, 8)>>>(wout, wo, DIM);

    // 1) qkv = x @ w_qkv  (mma.sync bf16, 3-way split)
    mma_gemm_kernel<<<dim3(QKV_COLS / 128, MROWS / 128), 256, GSMEM_BYTES>>>(
        aq, wq, qkvp, QKV_COLS);

    // 2) flash attention
    attn_kernel<<<dim3(SEQ / 128, BATCH * HEADS), 256, ATTN_SMEM_BYTES>>>(
        qkvp, smask, attp);

    // 3) out = att @ w_out (mma.sync bf16, 3-way split)
    split_a_kernel<<<MROWS * 1024 / 256, 256>>>(attp, a2q, MROWS);
    mma_gemm_kernel<<<dim3(DIM / 128, MROWS / 128), 256, GSMEM_BYTES>>>(
        a2q, wo, out, DIM);
}

// round 5
// speedup vs baseline: 2.2896x; 1.6748x over previous
#include <cuda_runtime.h>
#include <cuda_bf16.h>
#include <cstdint>
#include <math.h>

// Problem constants
#define BATCH 2
#define SEQ   2048
#define DIM   1024
#define HEADS 16
#define DHEAD 64
#define INNER 1024
#define QKV_COLS 3072
#define MROWS 4096              // BATCH*SEQ
#define KP    3072              // split-K': 3*1024
#define ATT_SCALE 0.125f

// Scratch (device globals — no cudaMalloc allowed)
__device__ __nv_bfloat16 g_Aq [(size_t)MROWS * KP];           // x split [hi|hi|lo]
__device__ __nv_bfloat16 g_Wq [(size_t)QKV_COLS * KP];        // w_qkv^T split [hi|lo|hi]
__device__ __nv_bfloat16 g_Wo [(size_t)DIM * KP];             // w_out^T split
__device__ __nv_bfloat16 g_A2q[(size_t)MROWS * KP];           // attn out split [hi|hi|lo]
__device__ __nv_bfloat16 g_qh[(size_t)MROWS * INNER];         // Q hi  [b*n][h*64+d]
__device__ __nv_bfloat16 g_ql[(size_t)MROWS * INNER];
__device__ __nv_bfloat16 g_kh[(size_t)MROWS * INNER];
__device__ __nv_bfloat16 g_kl[(size_t)MROWS * INNER];
__device__ __nv_bfloat16 g_vth[(size_t)32 * 64 * SEQ];        // V^T hi [bh][d][n]
__device__ __nv_bfloat16 g_vtl[(size_t)32 * 64 * SEQ];
__device__ float g_vst[(size_t)MROWS * INNER];                // V fp32 staging

// ---------------------------------------------------------------------------
// PTX helpers (sm_80-compatible only; harness lowers via virtual compute_103)
// ---------------------------------------------------------------------------
__device__ __forceinline__ uint32_t smem_u32(const void* p) {
    uint32_t a;
    asm("{ .reg .u64 t; cvta.to.shared.u64 t, %1; cvt.u32.u64 %0, t; }"
        : "=r"(a) : "l"(p));
    return a;
}
#define SWZ128(o) ((o) ^ (((o) >> 3) & 0x70))
#define CP16(dst, src)  asm volatile("cp.async.cg.shared.global [%0], [%1], 16;" :: "r"(dst), "l"(src) : "memory")
#define CP_COMMIT()     asm volatile("cp.async.commit_group;" ::: "memory")
#define CP_WAIT1()      asm volatile("cp.async.wait_group 1;" ::: "memory")
#define CP_WAIT0()      asm volatile("cp.async.wait_group 0;" ::: "memory")

#define LDSM4(r0, r1, r2, r3, addr) \
    asm volatile("ldmatrix.sync.aligned.m8n8.x4.shared.b16 {%0,%1,%2,%3}, [%4];" \
                 : "=r"(r0), "=r"(r1), "=r"(r2), "=r"(r3) : "r"(addr))

#define MMA16816(d, a, b0, b1) \
    asm volatile("mma.sync.aligned.m16n8k16.row.col.f32.bf16.bf16.f32 " \
                 "{%0,%1,%2,%3}, {%4,%5,%6,%7}, {%8,%9}, {%0,%1,%2,%3};" \
                 : "+f"((d)[0]), "+f"((d)[1]), "+f"((d)[2]), "+f"((d)[3]) \
                 : "r"((a)[0]), "r"((a)[1]), "r"((a)[2]), "r"((a)[3]), \
                   "r"(b0), "r"(b1))

// split two fp32 -> packed bf16 hi-pair / lo-pair
__device__ __forceinline__ void split2(float v0, float v1,
                                       uint32_t& hi, uint32_t& lo) {
    __nv_bfloat16 h0 = __float2bfloat16(v0), h1 = __float2bfloat16(v1);
    __nv_bfloat16 l0 = __float2bfloat16(v0 - __bfloat162float(h0));
    __nv_bfloat16 l1 = __float2bfloat16(v1 - __bfloat162float(h1));
    hi = ((uint32_t)__bfloat16_as_ushort(h1) << 16) | __bfloat16_as_ushort(h0);
    lo = ((uint32_t)__bfloat16_as_ushort(l1) << 16) | __bfloat16_as_ushort(l0);
}

// ---------------------------------------------------------------------------
// Input split kernels
// ---------------------------------------------------------------------------
__global__ void split_a_kernel(const float* __restrict__ in,
                               __nv_bfloat16* __restrict__ out, int rows)
{
    int idx = blockIdx.x * 256 + threadIdx.x;
    if (idx >= rows * 1024) return;
    int m = idx >> 10, k = idx & 1023;
    float v = in[idx];
    __nv_bfloat16 hi = __float2bfloat16(v);
    __nv_bfloat16 lo = __float2bfloat16(v - __bfloat162float(hi));
    size_t o = (size_t)m * KP + k;
    out[o] = hi; out[o + 1024] = hi; out[o + 2048] = lo;
}

__global__ void split_w_kernel(const float* __restrict__ w,
                               __nv_bfloat16* __restrict__ out, int N)
{
    __shared__ float t[32][33];
    int bk = blockIdx.y * 32, bn = blockIdx.x * 32;
    int tx = threadIdx.x, ty = threadIdx.y;   // (32, 8)
#pragma unroll
    for (int i = 0; i < 4; i++)
        t[ty + 8 * i][tx] = w[(size_t)(bk + ty + 8 * i) * N + bn + tx];
    __syncthreads();
#pragma unroll
    for (int i = 0; i < 4; i++) {
        int n = bn + ty + 8 * i, k = bk + tx;
        float v = t[tx][ty + 8 * i];
        __nv_bfloat16 hi = __float2bfloat16(v);
        __nv_bfloat16 lo = __float2bfloat16(v - __bfloat162float(hi));
        size_t o = (size_t)n * KP + k;
        out[o] = hi; out[o + 1024] = lo; out[o + 2048] = hi;
    }
}

// V fp32 staging [b*n][h*64+d] -> V^T hi/lo [bh][d][n]
__global__ void split_vt_kernel(const float* __restrict__ vst,
                                __nv_bfloat16* __restrict__ vth,
                                __nv_bfloat16* __restrict__ vtl)
{
    __shared__ float t[32][33];
    int bh = blockIdx.z, b = bh >> 4, h = bh & 15;
    int n0 = blockIdx.x * 32, d0 = blockIdx.y * 32;
    int tx = threadIdx.x, ty = threadIdx.y;   // (32, 8)
#pragma unroll
    for (int i = 0; i < 4; i++)
        t[ty + 8 * i][tx] =
            vst[(size_t)(b * SEQ + n0 + ty + 8 * i) * 1024 + h * 64 + d0 + tx];
    __syncthreads();
#pragma unroll
    for (int i = 0; i < 4; i++) {
        int d = d0 + ty + 8 * i;
        float v = t[tx][ty + 8 * i];
        __nv_bfloat16 hi = __float2bfloat16(v);
        __nv_bfloat16 lo = __float2bfloat16(v - __bfloat162float(hi));
        size_t o = (size_t)(bh * 64 + d) * SEQ + n0 + tx;
        vth[o] = hi; vtl[o] = lo;
    }
}

// ---------------------------------------------------------------------------
// bf16 GEMM via mma.sync (proven R4 core). mode 0: fp32 C. mode 1: QKV —
// cols [0,1024) -> Q hi/lo bf16, [1024,2048) -> K hi/lo, [2048,3072) -> V fp32.
// ---------------------------------------------------------------------------
#define GSTAGES 3
#define STAGE_BYTES 32768
#define GSMEM_BYTES (GSTAGES * STAGE_BYTES)
#define NCHUNK (KP / 64)     // 48

__device__ __forceinline__ void gemm_load_chunk(
    uint32_t sb, int stage, int chunk, int tid,
    const __nv_bfloat16* __restrict__ A, const __nv_bfloat16* __restrict__ B,
    int row0, int col0)
{
    uint32_t sA = sb + stage * STAGE_BYTES;
    uint32_t sB = sA + 16384;
    int k0 = chunk * 64;
#pragma unroll
    for (int i = 0; i < 4; i++) {
        int g = tid + i * 256;
        int row = g >> 3, c16 = g & 7;
        uint32_t off = SWZ128((uint32_t)(row * 128 + c16 * 16));
        CP16(sA + off, A + (size_t)(row0 + row) * KP + k0 + c16 * 8);
        CP16(sB + off, B + (size_t)(col0 + row) * KP + k0 + c16 * 8);
    }
}

__global__ __launch_bounds__(256, 2)
void mma_gemm_kernel(const __nv_bfloat16* __restrict__ A,
                     const __nv_bfloat16* __restrict__ B,
                     float* __restrict__ C, int N, int mode,
                     __nv_bfloat16* __restrict__ qh, __nv_bfloat16* __restrict__ ql,
                     __nv_bfloat16* __restrict__ kh, __nv_bfloat16* __restrict__ kl,
                     float* __restrict__ vst)
{
    extern __shared__ char smem[];
    uint32_t sb = smem_u32(smem);
    const int tid  = threadIdx.x;
    const int lane = tid & 31;
    const int wid  = tid >> 5;
    const int wm   = wid & 3;
    const int wn   = wid >> 2;
    const int row0 = blockIdx.y * 128;
    const int col0 = blockIdx.x * 128;

    float acc[2][8][4];
#pragma unroll
    for (int mt = 0; mt < 2; mt++)
#pragma unroll
        for (int nt = 0; nt < 8; nt++)
#pragma unroll
            for (int v = 0; v < 4; v++) acc[mt][nt][v] = 0.0f;

    gemm_load_chunk(sb, 0, 0, tid, A, B, row0, col0);
    CP_COMMIT();
    gemm_load_chunk(sb, 1, 1, tid, A, B, row0, col0);
    CP_COMMIT();

    const int arow_l = wm * 32 + (lane & 15);
    const int brow_l = wn * 64 + (lane & 15);
    const int khalf  = (lane >> 4) * 16;

    for (int c = 0; c < NCHUNK; c++) {
        CP_WAIT1();
        __syncthreads();

        int nc = c + 2;
        if (nc < NCHUNK)
            gemm_load_chunk(sb, nc % 3, nc, tid, A, B, row0, col0);
        CP_COMMIT();

        uint32_t sA = sb + (c % 3) * STAGE_BYTES;
        uint32_t sB = sA + 16384;

#pragma unroll
        for (int ks = 0; ks < 4; ks++) {
            const int kb = ks * 32 + khalf;
            uint32_t a[2][4], b[4][4];
#pragma unroll
            for (int mt = 0; mt < 2; mt++) {
                uint32_t ad = sA + SWZ128((uint32_t)((arow_l + mt * 16) * 128 + kb));
                LDSM4(a[mt][0], a[mt][1], a[mt][2], a[mt][3], ad);
            }
#pragma unroll
            for (int np = 0; np < 4; np++) {
                uint32_t bd = sB + SWZ128((uint32_t)((brow_l + np * 16) * 128 + kb));
                LDSM4(b[np][0], b[np][1], b[np][2], b[np][3], bd);
            }
#pragma unroll
            for (int mt = 0; mt < 2; mt++)
#pragma unroll
                for (int nt = 0; nt < 8; nt++) {
                    int np = nt >> 1, sel = nt & 1;
                    MMA16816(acc[mt][nt], a[mt], b[np][sel], b[np][2 + sel]);
                }
        }
    }

    const int g = lane >> 2, t = lane & 3;
#pragma unroll
    for (int mt = 0; mt < 2; mt++) {
        int r0 = row0 + wm * 32 + mt * 16 + g;
#pragma unroll
        for (int nt = 0; nt < 8; nt++) {
            int col = col0 + wn * 64 + nt * 8 + t * 2;
            if (mode == 0) {
                *(float2*)&C[(size_t)r0 * N + col] =
                    make_float2(acc[mt][nt][0], acc[mt][nt][1]);
                *(float2*)&C[(size_t)(r0 + 8) * N + col] =
                    make_float2(acc[mt][nt][2], acc[mt][nt][3]);
            } else {
                int sec = col >> 10, cc = col & 1023;
                if (sec == 2) {
                    *(float2*)&vst[(size_t)r0 * 1024 + cc] =
                        make_float2(acc[mt][nt][0], acc[mt][nt][1]);
                    *(float2*)&vst[(size_t)(r0 + 8) * 1024 + cc] =
                        make_float2(acc[mt][nt][2], acc[mt][nt][3]);
                } else {
                    __nv_bfloat16* dh = sec ? kh : qh;
                    __nv_bfloat16* dl = sec ? kl : ql;
                    uint32_t hi, lo;
                    split2(acc[mt][nt][0], acc[mt][nt][1], hi, lo);
                    *(uint32_t*)&dh[(size_t)r0 * 1024 + cc] = hi;
                    *(uint32_t*)&dl[(size_t)r0 * 1024 + cc] = lo;
                    split2(acc[mt][nt][2], acc[mt][nt][3], hi, lo);
                    *(uint32_t*)&dh[(size_t)(r0 + 8) * 1024 + cc] = hi;
                    *(uint32_t*)&dl[(size_t)(r0 + 8) * 1024 + cc] = lo;
                }
            }
        }
    }
}

// ---------------------------------------------------------------------------
// Flash attention on mma.sync bf16 (3-term split both matmuls).
// grid (16 i-tiles, 32 bh), 256 threads = 8 warps; warp w owns rows w*16..+15.
// SMEM layout (bytes):
//   QH 0, QL 16384 (128x64 bf16, 128B rows)
//   stages s=0,1 at 32768 + s*65536: KH+0, KL+16384 (128x64),
//                                    VH+32768, VL+49152 (64 d-rows x 128 j, 256B rows)
//   PH 163840, PL 196608 (128 i-rows x 128 j, 256B rows)
//   MASK 229376 + s*512
// ---------------------------------------------------------------------------
#define AT_QH   0
#define AT_QL   16384
#define AT_STG  32768
#define AT_KH   0
#define AT_KL   16384
#define AT_VH   32768
#define AT_VL   49152
#define AT_PH   163840
#define AT_PL   196608
#define AT_MASK 229376
#define AT_SMEM 230400

__device__ __forceinline__ void attn_load_stage(
    uint32_t sb, int stage, int j0, int tid, int b, int bh,
    const __nv_bfloat16* __restrict__ kh, const __nv_bfloat16* __restrict__ kl,
    const __nv_bfloat16* __restrict__ vth, const __nv_bfloat16* __restrict__ vtl,
    const float* __restrict__ mask)
{
    uint32_t st = sb + AT_STG + stage * 65536;
    const int h = bh & 15;
    const __nv_bfloat16* khg = kh + (size_t)(b * SEQ + j0) * 1024 + h * 64;
    const __nv_bfloat16* klg = kl + (size_t)(b * SEQ + j0) * 1024 + h * 64;
#pragma unroll
    for (int i = 0; i < 4; i++) {
        int t = tid + i * 256;          // 0..1023
        int row = t >> 3, c = t & 7;
        uint32_t off = SWZ128((uint32_t)(row * 128 + c * 16));
        CP16(st + AT_KH + off, khg + (size_t)row * 1024 + c * 8);
        CP16(st + AT_KL + off, klg + (size_t)row * 1024 + c * 8);
    }
    const __nv_bfloat16* vhg = vth + (size_t)(bh * 64) * SEQ + j0;
    const __nv_bfloat16* vlg = vtl + (size_t)(bh * 64) * SEQ + j0;
#pragma unroll
    for (int i = 0; i < 4; i++) {
        int t = tid + i * 256;          // 0..1023
        int d = t >> 4, c = t & 15;
        uint32_t off = SWZ128((uint32_t)(d * 256 + c * 16));
        CP16(st + AT_VH + off, vhg + (size_t)d * SEQ + c * 8);
        CP16(st + AT_VL + off, vlg + (size_t)d * SEQ + c * 8);
    }
    if (tid < 32)
        CP16(sb + AT_MASK + stage * 512 + tid * 16, mask + b * SEQ + j0 + tid * 4);
}

__global__ __launch_bounds__(256, 1)
void attn_mma_kernel(const __nv_bfloat16* __restrict__ qh,
                     const __nv_bfloat16* __restrict__ ql,
                     const __nv_bfloat16* __restrict__ kh,
                     const __nv_bfloat16* __restrict__ kl,
                     const __nv_bfloat16* __restrict__ vth,
                     const __nv_bfloat16* __restrict__ vtl,
                     const float* __restrict__ mask,
                     __nv_bfloat16* __restrict__ a2q)
{
    extern __shared__ char smem[];
    uint32_t sb = smem_u32(smem);
    const int tid = threadIdx.x, lane = tid & 31, w = tid >> 5;
    const int g = lane >> 2, t4 = lane & 3;
    const int l16 = lane & 15, khalf = (lane >> 4) * 16;
    const int bh = blockIdx.y, b = bh >> 4, h = bh & 15;
    const int i0 = blockIdx.x * 128;

    // Q tile (hi+lo)
    {
        const __nv_bfloat16* qhg = qh + (size_t)(b * SEQ + i0) * 1024 + h * 64;
        const __nv_bfloat16* qlg = ql + (size_t)(b * SEQ + i0) * 1024 + h * 64;
#pragma unroll
        for (int i = 0; i < 4; i++) {
            int t = tid + i * 256;
            int row = t >> 3, c = t & 7;
            uint32_t off = SWZ128((uint32_t)(row * 128 + c * 16));
            CP16(sb + AT_QH + off, qhg + (size_t)row * 1024 + c * 8);
            CP16(sb + AT_QL + off, qlg + (size_t)row * 1024 + c * 8);
        }
    }
    attn_load_stage(sb, 0, 0, tid, b, bh, kh, kl, vth, vtl, mask);
    CP_COMMIT();

    float m0 = -1e30f, m1 = -1e30f, lsum0 = 0.0f, lsum1 = 0.0f;
    float o[8][4];
#pragma unroll
    for (int nt = 0; nt < 8; nt++)
#pragma unroll
        for (int v = 0; v < 4; v++) o[nt][v] = 0.0f;

    const uint32_t arow_off = (uint32_t)((w * 16 + l16) * 128);   // Q/K rows
    const uint32_t prow_off = (uint32_t)((w * 16 + l16) * 256);   // P rows

    for (int jt = 0; jt < 16; jt++) {
        CP_WAIT0();
        __syncthreads();
        if (jt + 1 < 16)
            attn_load_stage(sb, (jt + 1) & 1, (jt + 1) * 128, tid, b, bh,
                            kh, kl, vth, vtl, mask);
        CP_COMMIT();

        uint32_t stg = sb + AT_STG + (jt & 1) * 65536;
        const float* maskS = (const float*)(smem + AT_MASK + (jt & 1) * 512);

        // ---- S = Q K^T (3 split passes) ----
        float s[16][4];
#pragma unroll
        for (int nt = 0; nt < 16; nt++)
#pragma unroll
            for (int v = 0; v < 4; v++) s[nt][v] = 0.0f;

#pragma unroll
        for (int pass = 0; pass < 3; pass++) {
            uint32_t ap = sb + (pass == 2 ? AT_QL : AT_QH);
            uint32_t bp = stg + (pass == 1 ? AT_KL : AT_KH);
#pragma unroll
            for (int ks = 0; ks < 4; ks++) {
                const uint32_t kb = ks * 32 + khalf;
                uint32_t a4[4];
                LDSM4(a4[0], a4[1], a4[2], a4[3], ap + SWZ128(arow_off + kb));
#pragma unroll
                for (int np = 0; np < 8; np++) {
                    uint32_t b4[4];
                    LDSM4(b4[0], b4[1], b4[2], b4[3],
                          bp + SWZ128((uint32_t)((np * 16 + l16) * 128 + kb)));
                    MMA16816(s[np * 2], a4, b4[0], b4[2]);
                    MMA16816(s[np * 2 + 1], a4, b4[1], b4[3]);
                }
            }
        }

        // ---- mask*scale, online softmax ----
        float rm0 = -1e30f, rm1 = -1e30f;
#pragma unroll
        for (int nt = 0; nt < 16; nt++) {
            float2 mk = *(const float2*)&maskS[nt * 8 + t4 * 2];
            mk.x *= ATT_SCALE; mk.y *= ATT_SCALE;
            s[nt][0] *= mk.x; s[nt][1] *= mk.y;
            s[nt][2] *= mk.x; s[nt][3] *= mk.y;
            rm0 = fmaxf(rm0, fmaxf(s[nt][0], s[nt][1]));
            rm1 = fmaxf(rm1, fmaxf(s[nt][2], s[nt][3]));
        }
        rm0 = fmaxf(rm0, __shfl_xor_sync(0xffffffffu, rm0, 1));
        rm0 = fmaxf(rm0, __shfl_xor_sync(0xffffffffu, rm0, 2));
        rm1 = fmaxf(rm1, __shfl_xor_sync(0xffffffffu, rm1, 1));
        rm1 = fmaxf(rm1, __shfl_xor_sync(0xffffffffu, rm1, 2));
        float mn0 = fmaxf(m0, rm0), mn1 = fmaxf(m1, rm1);
        float al0 = __expf(m0 - mn0), al1 = __expf(m1 - mn1);
        m0 = mn0; m1 = mn1;
        lsum0 *= al0; lsum1 *= al1;
#pragma unroll
        for (int nt = 0; nt < 8; nt++) {
            o[nt][0] *= al0; o[nt][1] *= al0;
            o[nt][2] *= al1; o[nt][3] *= al1;
        }

        // ---- exp, split P to bf16 hi/lo, stage to warp-private smem rows ----
        const int pr0 = (w * 16 + g) * 256, pr1 = (w * 16 + g + 8) * 256;
        float ps0 = 0.0f, ps1 = 0.0f;
#pragma unroll
        for (int nt = 0; nt < 16; nt++) {
            float p0 = __expf(s[nt][0] - m0), p1 = __expf(s[nt][1] - m0);
            float p2 = __expf(s[nt][2] - m1), p3 = __expf(s[nt][3] - m1);
            ps0 += p0 + p1; ps1 += p2 + p3;
            uint32_t hi, lo;
            const uint32_t colb = nt * 16 + t4 * 4;
            split2(p0, p1, hi, lo);
            *(uint32_t*)(smem + AT_PH + SWZ128((uint32_t)(pr0 + colb))) = hi;
            *(uint32_t*)(smem + AT_PL + SWZ128((uint32_t)(pr0 + colb))) = lo;
            split2(p2, p3, hi, lo);
            *(uint32_t*)(smem + AT_PH + SWZ128((uint32_t)(pr1 + colb))) = hi;
            *(uint32_t*)(smem + AT_PL + SWZ128((uint32_t)(pr1 + colb))) = lo;
        }
        lsum0 += ps0; lsum1 += ps1;
        __syncwarp();

        // ---- O += P V (3 split passes) ----
#pragma unroll
        for (int pass = 0; pass < 3; pass++) {
            uint32_t ap = sb + (pass == 2 ? AT_PL : AT_PH);
            uint32_t bp = stg + (pass == 1 ? AT_VL : AT_VH);
#pragma unroll
            for (int ks = 0; ks < 8; ks++) {
                const uint32_t kb = ks * 32 + khalf;
                uint32_t a4[4];
                LDSM4(a4[0], a4[1], a4[2], a4[3], ap + SWZ128(prow_off + kb));
#pragma unroll
                for (int np = 0; np < 4; np++) {
                    uint32_t b4[4];
                    LDSM4(b4[0], b4[1], b4[2], b4[3],
                          bp + SWZ128((uint32_t)((np * 16 + l16) * 256 + kb)));
                    MMA16816(o[np * 2], a4, b4[0], b4[2]);
                    MMA16816(o[np * 2 + 1], a4, b4[1], b4[3]);
                }
            }
        }
        __syncwarp();
    }

    // ---- finalize: reduce l over quad, normalize, write split A' for GEMM3 ----
    lsum0 += __shfl_xor_sync(0xffffffffu, lsum0, 1);
    lsum0 += __shfl_xor_sync(0xffffffffu, lsum0, 2);
    lsum1 += __shfl_xor_sync(0xffffffffu, lsum1, 1);
    lsum1 += __shfl_xor_sync(0xffffffffu, lsum1, 2);
    float inv0 = 1.0f / lsum0, inv1 = 1.0f / lsum1;

    const int r0 = i0 + w * 16 + g, r1 = r0 + 8;
#pragma unroll
    for (int nt = 0; nt < 8; nt++) {
        int col = nt * 8 + t4 * 2;
        uint32_t hi, lo;
        size_t base0 = (size_t)(b * SEQ + r0) * KP + h * 64 + col;
        split2(o[nt][0] * inv0, o[nt][1] * inv0, hi, lo);
        *(uint32_t*)&a2q[base0]        = hi;
        *(uint32_t*)&a2q[base0 + 1024] = hi;
        *(uint32_t*)&a2q[base0 + 2048] = lo;
        size_t base1 = (size_t)(b * SEQ + r1) * KP + h * 64 + col;
        split2(o[nt][2] * inv1, o[nt][3] * inv1, hi, lo);
        *(uint32_t*)&a2q[base1]        = hi;
        *(uint32_t*)&a2q[base1 + 1024] = hi;
        *(uint32_t*)&a2q[base1 + 2048] = lo;
    }
}

// ---------------------------------------------------------------------------
// Launch
// ---------------------------------------------------------------------------
extern "C" void kernel_launch(void* const* d_in, const int* in_sizes, int n_in,
                              void* d_out, int out_size)
{
    const float* x     = (const float*)d_in[0];
    const float* smask = (const float*)d_in[1];
    const float* wqkv  = (const float*)d_in[2];
    const float* wout  = (const float*)d_in[3];
    float* out = (float*)d_out;

    __nv_bfloat16 *aq, *wq, *wo, *a2q, *qhp, *qlp, *khp, *klp, *vthp, *vtlp;
    float* vstp;
    cudaGetSymbolAddress((void**)&aq,  g_Aq);
    cudaGetSymbolAddress((void**)&wq,  g_Wq);
    cudaGetSymbolAddress((void**)&wo,  g_Wo);
    cudaGetSymbolAddress((void**)&a2q, g_A2q);
    cudaGetSymbolAddress((void**)&qhp, g_qh);
    cudaGetSymbolAddress((void**)&qlp, g_ql);
    cudaGetSymbolAddress((void**)&khp, g_kh);
    cudaGetSymbolAddress((void**)&klp, g_kl);
    cudaGetSymbolAddress((void**)&vthp, g_vth);
    cudaGetSymbolAddress((void**)&vtlp, g_vtl);
    cudaGetSymbolAddress((void**)&vstp, g_vst);

    cudaFuncSetAttribute(mma_gemm_kernel, cudaFuncAttributeMaxDynamicSharedMemorySize,
                         GSMEM_BYTES);
    cudaFuncSetAttribute(attn_mma_kernel, cudaFuncAttributeMaxDynamicSharedMemorySize,
                         AT_SMEM);

    // 0) split inputs
    split_a_kernel<<<MROWS * 1024 / 256, 256>>>(x, aq, MROWS);
    split_w_kernel<<<dim3(QKV_COLS / 32, 32), dim3(32, 8)>>>(wqkv, wq, QKV_COLS);
    split_w_kernel<<<dim3(DIM / 32, 32), dim3(32, 8)>>>(wout, wo, DIM);

    // 1) qkv GEMM, epilogue splits Q/K to bf16 and stages V fp32
    mma_gemm_kernel<<<dim3(QKV_COLS / 128, MROWS / 128), 256, GSMEM_BYTES>>>(
        aq, wq, nullptr, QKV_COLS, 1, qhp, qlp, khp, klp, vstp);

    // 1b) V transpose + split
    split_vt_kernel<<<dim3(SEQ / 32, 2, 32), dim3(32, 8)>>>(vstp, vthp, vtlp);

    // 2) flash attention on tensor pipe; epilogue writes split A' for GEMM3
    attn_mma_kernel<<<dim3(SEQ / 128, BATCH * HEADS), 256, AT_SMEM>>>(
        qhp, qlp, khp, klp, vthp, vtlp, smask, a2q);

    // 3) out projection
    mma_gemm_kernel<<<dim3(DIM / 128, MROWS / 128), 256, GSMEM_BYTES>>>(
        a2q, wo, out, DIM, 0, nullptr, nullptr, nullptr, nullptr, nullptr);
}

// round 6
// speedup vs baseline: 3.0118x; 1.3154x over previous
#include <cuda_runtime.h>
#include <cuda_bf16.h>
#include <cstdint>
#include <math.h>

// Problem constants
#define BATCH 2
#define SEQ   2048
#define DIM   1024
#define HEADS 16
#define DHEAD 64
#define INNER 1024
#define QKV_COLS 3072
#define MROWS 4096              // BATCH*SEQ
#define KP    3072              // split-K': 3*1024
#define ATT_SCALE 0.125f
#define LOG2E 1.4426950408889634f

// Scratch (device globals — no cudaMalloc allowed)
__device__ __nv_bfloat16 g_Aq [(size_t)MROWS * KP];           // x split [hi|hi|lo]
__device__ __nv_bfloat16 g_Wq [(size_t)QKV_COLS * KP];        // w_qkv^T split [hi|lo|hi]
__device__ __nv_bfloat16 g_Wo [(size_t)DIM * KP];             // w_out^T split
__device__ __nv_bfloat16 g_A2q[(size_t)MROWS * KP];           // attn out split [hi|hi|lo]
__device__ __nv_bfloat16 g_qh[(size_t)MROWS * INNER];         // Q hi  [b*n][h*64+d]
__device__ __nv_bfloat16 g_ql[(size_t)MROWS * INNER];
__device__ __nv_bfloat16 g_kh[(size_t)MROWS * INNER];
__device__ __nv_bfloat16 g_kl[(size_t)MROWS * INNER];
__device__ __nv_bfloat16 g_vth[(size_t)32 * 64 * SEQ];        // V^T hi [bh][d][n]
__device__ __nv_bfloat16 g_vtl[(size_t)32 * 64 * SEQ];
__device__ float g_vst[(size_t)MROWS * INNER];                // V fp32 staging

// ---------------------------------------------------------------------------
// PTX helpers (sm_80-compatible only; harness lowers via virtual compute_103)
// ---------------------------------------------------------------------------
__device__ __forceinline__ uint32_t smem_u32(const void* p) {
    uint32_t a;
    asm("{ .reg .u64 t; cvta.to.shared.u64 t, %1; cvt.u32.u64 %0, t; }"
        : "=r"(a) : "l"(p));
    return a;
}
#define SWZ128(o) ((o) ^ (((o) >> 3) & 0x70))
#define SWZ256(o) ((o) ^ (((o) >> 4) & 0x70))
#define CP16(dst, src)  asm volatile("cp.async.cg.shared.global [%0], [%1], 16;" :: "r"(dst), "l"(src) : "memory")
#define CP_COMMIT()     asm volatile("cp.async.commit_group;" ::: "memory")
#define CP_WAIT1()      asm volatile("cp.async.wait_group 1;" ::: "memory")
#define CP_WAIT0()      asm volatile("cp.async.wait_group 0;" ::: "memory")

#define LDSM4(r0, r1, r2, r3, addr) \
    asm volatile("ldmatrix.sync.aligned.m8n8.x4.shared.b16 {%0,%1,%2,%3}, [%4];" \
                 : "=r"(r0), "=r"(r1), "=r"(r2), "=r"(r3) : "r"(addr))

#define MMA16816(d, a, b0, b1) \
    asm volatile("mma.sync.aligned.m16n8k16.row.col.f32.bf16.bf16.f32 " \
                 "{%0,%1,%2,%3}, {%4,%5,%6,%7}, {%8,%9}, {%0,%1,%2,%3};" \
                 : "+f"((d)[0]), "+f"((d)[1]), "+f"((d)[2]), "+f"((d)[3]) \
                 : "r"((a)[0]), "r"((a)[1]), "r"((a)[2]), "r"((a)[3]), \
                   "r"(b0), "r"(b1))

// pack two fp32 -> bf16x2 (lo in low half)
__device__ __forceinline__ uint32_t packbf(float lo, float hi) {
    uint32_t r;
    asm("cvt.rn.bf16x2.f32 %0, %1, %2;" : "=r"(r) : "f"(hi), "f"(lo));
    return r;
}
// split two fp32 -> packed bf16 hi-pair / lo-pair
__device__ __forceinline__ void split2(float v0, float v1,
                                       uint32_t& hi, uint32_t& lo) {
    hi = packbf(v0, v1);
    float h0 = __uint_as_float(hi << 16);
    float h1 = __uint_as_float(hi & 0xffff0000u);
    lo = packbf(v0 - h0, v1 - h1);
}

// ---------------------------------------------------------------------------
// Input split kernels
// ---------------------------------------------------------------------------
__global__ void split_a_kernel(const float* __restrict__ in,
                               __nv_bfloat16* __restrict__ out, int rows)
{
    int idx = blockIdx.x * 256 + threadIdx.x;
    if (idx >= rows * 1024) return;
    int m = idx >> 10, k = idx & 1023;
    float v = in[idx];
    __nv_bfloat16 hi = __float2bfloat16(v);
    __nv_bfloat16 lo = __float2bfloat16(v - __bfloat162float(hi));
    size_t o = (size_t)m * KP + k;
    out[o] = hi; out[o + 1024] = hi; out[o + 2048] = lo;
}

__global__ void split_w_kernel(const float* __restrict__ w,
                               __nv_bfloat16* __restrict__ out, int N)
{
    __shared__ float t[32][33];
    int bk = blockIdx.y * 32, bn = blockIdx.x * 32;
    int tx = threadIdx.x, ty = threadIdx.y;   // (32, 8)
#pragma unroll
    for (int i = 0; i < 4; i++)
        t[ty + 8 * i][tx] = w[(size_t)(bk + ty + 8 * i) * N + bn + tx];
    __syncthreads();
#pragma unroll
    for (int i = 0; i < 4; i++) {
        int n = bn + ty + 8 * i, k = bk + tx;
        float v = t[tx][ty + 8 * i];
        __nv_bfloat16 hi = __float2bfloat16(v);
        __nv_bfloat16 lo = __float2bfloat16(v - __bfloat162float(hi));
        size_t o = (size_t)n * KP + k;
        out[o] = hi; out[o + 1024] = lo; out[o + 2048] = hi;
    }
}

// V fp32 staging [b*n][h*64+d] -> V^T hi/lo [bh][d][n]
__global__ void split_vt_kernel(const float* __restrict__ vst,
                                __nv_bfloat16* __restrict__ vth,
                                __nv_bfloat16* __restrict__ vtl)
{
    __shared__ float t[32][33];
    int bh = blockIdx.z, b = bh >> 4, h = bh & 15;
    int n0 = blockIdx.x * 32, d0 = blockIdx.y * 32;
    int tx = threadIdx.x, ty = threadIdx.y;   // (32, 8)
#pragma unroll
    for (int i = 0; i < 4; i++)
        t[ty + 8 * i][tx] =
            vst[(size_t)(b * SEQ + n0 + ty + 8 * i) * 1024 + h * 64 + d0 + tx];
    __syncthreads();
#pragma unroll
    for (int i = 0; i < 4; i++) {
        int d = d0 + ty + 8 * i;
        float v = t[tx][ty + 8 * i];
        __nv_bfloat16 hi = __float2bfloat16(v);
        __nv_bfloat16 lo = __float2bfloat16(v - __bfloat162float(hi));
        size_t o = (size_t)(bh * 64 + d) * SEQ + n0 + tx;
        vth[o] = hi; vtl[o] = lo;
    }
}

// ---------------------------------------------------------------------------
// bf16 GEMM via mma.sync (proven core). mode 0: fp32 C. mode 1: QKV epilogue.
// ---------------------------------------------------------------------------
#define GSTAGES 3
#define STAGE_BYTES 32768
#define GSMEM_BYTES (GSTAGES * STAGE_BYTES)
#define NCHUNK (KP / 64)     // 48

__device__ __forceinline__ void gemm_load_chunk(
    uint32_t sb, int stage, int chunk, int tid,
    const __nv_bfloat16* __restrict__ A, const __nv_bfloat16* __restrict__ B,
    int row0, int col0)
{
    uint32_t sA = sb + stage * STAGE_BYTES;
    uint32_t sB = sA + 16384;
    int k0 = chunk * 64;
#pragma unroll
    for (int i = 0; i < 4; i++) {
        int g = tid + i * 256;
        int row = g >> 3, c16 = g & 7;
        uint32_t off = SWZ128((uint32_t)(row * 128 + c16 * 16));
        CP16(sA + off, A + (size_t)(row0 + row) * KP + k0 + c16 * 8);
        CP16(sB + off, B + (size_t)(col0 + row) * KP + k0 + c16 * 8);
    }
}

__global__ __launch_bounds__(256, 2)
void mma_gemm_kernel(const __nv_bfloat16* __restrict__ A,
                     const __nv_bfloat16* __restrict__ B,
                     float* __restrict__ C, int N, int mode,
                     __nv_bfloat16* __restrict__ qh, __nv_bfloat16* __restrict__ ql,
                     __nv_bfloat16* __restrict__ kh, __nv_bfloat16* __restrict__ kl,
                     float* __restrict__ vst)
{
    extern __shared__ char smem[];
    uint32_t sb = smem_u32(smem);
    const int tid  = threadIdx.x;
    const int lane = tid & 31;
    const int wid  = tid >> 5;
    const int wm   = wid & 3;
    const int wn   = wid >> 2;
    const int row0 = blockIdx.y * 128;
    const int col0 = blockIdx.x * 128;

    float acc[2][8][4];
#pragma unroll
    for (int mt = 0; mt < 2; mt++)
#pragma unroll
        for (int nt = 0; nt < 8; nt++)
#pragma unroll
            for (int v = 0; v < 4; v++) acc[mt][nt][v] = 0.0f;

    gemm_load_chunk(sb, 0, 0, tid, A, B, row0, col0);
    CP_COMMIT();
    gemm_load_chunk(sb, 1, 1, tid, A, B, row0, col0);
    CP_COMMIT();

    const int arow_l = wm * 32 + (lane & 15);
    const int brow_l = wn * 64 + (lane & 15);
    const int khalf  = (lane >> 4) * 16;

    for (int c = 0; c < NCHUNK; c++) {
        CP_WAIT1();
        __syncthreads();

        int nc = c + 2;
        if (nc < NCHUNK)
            gemm_load_chunk(sb, nc % 3, nc, tid, A, B, row0, col0);
        CP_COMMIT();

        uint32_t sA = sb + (c % 3) * STAGE_BYTES;
        uint32_t sB = sA + 16384;

#pragma unroll
        for (int ks = 0; ks < 4; ks++) {
            const int kb = ks * 32 + khalf;
            uint32_t a[2][4], b[4][4];
#pragma unroll
            for (int mt = 0; mt < 2; mt++) {
                uint32_t ad = sA + SWZ128((uint32_t)((arow_l + mt * 16) * 128 + kb));
                LDSM4(a[mt][0], a[mt][1], a[mt][2], a[mt][3], ad);
            }
#pragma unroll
            for (int np = 0; np < 4; np++) {
                uint32_t bd = sB + SWZ128((uint32_t)((brow_l + np * 16) * 128 + kb));
                LDSM4(b[np][0], b[np][1], b[np][2], b[np][3], bd);
            }
#pragma unroll
            for (int mt = 0; mt < 2; mt++)
#pragma unroll
                for (int nt = 0; nt < 8; nt++) {
                    int np = nt >> 1, sel = nt & 1;
                    MMA16816(acc[mt][nt], a[mt], b[np][sel], b[np][2 + sel]);
                }
        }
    }

    const int g = lane >> 2, t = lane & 3;
#pragma unroll
    for (int mt = 0; mt < 2; mt++) {
        int r0 = row0 + wm * 32 + mt * 16 + g;
#pragma unroll
        for (int nt = 0; nt < 8; nt++) {
            int col = col0 + wn * 64 + nt * 8 + t * 2;
            if (mode == 0) {
                *(float2*)&C[(size_t)r0 * N + col] =
                    make_float2(acc[mt][nt][0], acc[mt][nt][1]);
                *(float2*)&C[(size_t)(r0 + 8) * N + col] =
                    make_float2(acc[mt][nt][2], acc[mt][nt][3]);
            } else {
                int sec = col >> 10, cc = col & 1023;
                if (sec == 2) {
                    *(float2*)&vst[(size_t)r0 * 1024 + cc] =
                        make_float2(acc[mt][nt][0], acc[mt][nt][1]);
                    *(float2*)&vst[(size_t)(r0 + 8) * 1024 + cc] =
                        make_float2(acc[mt][nt][2], acc[mt][nt][3]);
                } else {
                    __nv_bfloat16* dh = sec ? kh : qh;
                    __nv_bfloat16* dl = sec ? kl : ql;
                    uint32_t hi, lo;
                    split2(acc[mt][nt][0], acc[mt][nt][1], hi, lo);
                    *(uint32_t*)&dh[(size_t)r0 * 1024 + cc] = hi;
                    *(uint32_t*)&dl[(size_t)r0 * 1024 + cc] = lo;
                    split2(acc[mt][nt][2], acc[mt][nt][3], hi, lo);
                    *(uint32_t*)&dh[(size_t)(r0 + 8) * 1024 + cc] = hi;
                    *(uint32_t*)&dl[(size_t)(r0 + 8) * 1024 + cc] = lo;
                }
            }
        }
    }
}

// ---------------------------------------------------------------------------
// Flash attention on mma.sync bf16, register-resident Q and P fragments.
// grid (16 i-tiles, 32 bh), 256 threads = 8 warps; warp w owns rows w*16..+15.
// SMEM: QH 0, QL 16384 (128x64 bf16 rows 128B SWZ128)
//       stages s=0,1 at 32768+s*65536: KH+0, KL+16384 (128B rows SWZ128),
//                                      VH+32768, VL+49152 (64d x 128j, 256B rows SWZ256)
//       MASK 163840 + s*512. Total 164864.
// ---------------------------------------------------------------------------
#define AT_QH   0
#define AT_QL   16384
#define AT_STG  32768
#define AT_KH   0
#define AT_KL   16384
#define AT_VH   32768
#define AT_VL   49152
#define AT_MASK 163840
#define AT_SMEM 164864

__device__ __forceinline__ void attn_load_stage(
    uint32_t sb, int stage, int j0, int tid, int b, int bh,
    const __nv_bfloat16* __restrict__ kh, const __nv_bfloat16* __restrict__ kl,
    const __nv_bfloat16* __restrict__ vth, const __nv_bfloat16* __restrict__ vtl,
    const float* __restrict__ mask)
{
    uint32_t st = sb + AT_STG + stage * 65536;
    const int h = bh & 15;
    const __nv_bfloat16* khg = kh + (size_t)(b * SEQ + j0) * 1024 + h * 64;
    const __nv_bfloat16* klg = kl + (size_t)(b * SEQ + j0) * 1024 + h * 64;
#pragma unroll
    for (int i = 0; i < 4; i++) {
        int t = tid + i * 256;          // 0..1023
        int row = t >> 3, c = t & 7;
        uint32_t off = SWZ128((uint32_t)(row * 128 + c * 16));
        CP16(st + AT_KH + off, khg + (size_t)row * 1024 + c * 8);
        CP16(st + AT_KL + off, klg + (size_t)row * 1024 + c * 8);
    }
    const __nv_bfloat16* vhg = vth + (size_t)(bh * 64) * SEQ + j0;
    const __nv_bfloat16* vlg = vtl + (size_t)(bh * 64) * SEQ + j0;
#pragma unroll
    for (int i = 0; i < 4; i++) {
        int t = tid + i * 256;          // 0..1023
        int d = t >> 4, c = t & 15;
        uint32_t off = SWZ256((uint32_t)(d * 256 + c * 16));
        CP16(st + AT_VH + off, vhg + (size_t)d * SEQ + c * 8);
        CP16(st + AT_VL + off, vlg + (size_t)d * SEQ + c * 8);
    }
    if (tid < 32)
        CP16(sb + AT_MASK + stage * 512 + tid * 16, mask + b * SEQ + j0 + tid * 4);
}

__global__ __launch_bounds__(256)
void attn_mma_kernel(const __nv_bfloat16* __restrict__ qh,
                     const __nv_bfloat16* __restrict__ ql,
                     const __nv_bfloat16* __restrict__ kh,
                     const __nv_bfloat16* __restrict__ kl,
                     const __nv_bfloat16* __restrict__ vth,
                     const __nv_bfloat16* __restrict__ vtl,
                     const float* __restrict__ mask,
                     __nv_bfloat16* __restrict__ a2q)
{
    extern __shared__ char smem[];
    uint32_t sb = smem_u32(smem);
    const int tid = threadIdx.x, lane = tid & 31, w = tid >> 5;
    const int g = lane >> 2, t4 = lane & 3;
    const int l16 = lane & 15, khalf = (lane >> 4) * 16;
    const int bh = blockIdx.y, b = bh >> 4, h = bh & 15;
    const int i0 = blockIdx.x * 128;

    // async-load Q tile (hi+lo) as its own commit group
    {
        const __nv_bfloat16* qhg = qh + (size_t)(b * SEQ + i0) * 1024 + h * 64;
        const __nv_bfloat16* qlg = ql + (size_t)(b * SEQ + i0) * 1024 + h * 64;
#pragma unroll
        for (int i = 0; i < 4; i++) {
            int t = tid + i * 256;
            int row = t >> 3, c = t & 7;
            uint32_t off = SWZ128((uint32_t)(row * 128 + c * 16));
            CP16(sb + AT_QH + off, qhg + (size_t)row * 1024 + c * 8);
            CP16(sb + AT_QL + off, qlg + (size_t)row * 1024 + c * 8);
        }
    }
    CP_COMMIT();
    attn_load_stage(sb, 0, 0, tid, b, bh, kh, kl, vth, vtl, mask);
    CP_COMMIT();

    // Q fragments -> registers (dead smem afterwards)
    CP_WAIT1();
    __syncthreads();
    uint32_t qfh[4][4], qfl[4][4];
    const uint32_t qrow = (uint32_t)((w * 16 + l16) * 128);
#pragma unroll
    for (int ks = 0; ks < 4; ks++) {
        uint32_t kb = (uint32_t)(ks * 32 + khalf);
        LDSM4(qfh[ks][0], qfh[ks][1], qfh[ks][2], qfh[ks][3],
              sb + AT_QH + SWZ128(qrow + kb));
        LDSM4(qfl[ks][0], qfl[ks][1], qfl[ks][2], qfl[ks][3],
              sb + AT_QL + SWZ128(qrow + kb));
    }

    float m0 = -1e30f, m1 = -1e30f, lsum0 = 0.0f, lsum1 = 0.0f;
    float o[8][4];
#pragma unroll
    for (int nt = 0; nt < 8; nt++)
#pragma unroll
        for (int v = 0; v < 4; v++) o[nt][v] = 0.0f;

    const float MSC = ATT_SCALE * LOG2E;   // logits in log2 domain

    for (int jt = 0; jt < 16; jt++) {
        CP_WAIT0();
        __syncthreads();
        if (jt + 1 < 16)
            attn_load_stage(sb, (jt + 1) & 1, (jt + 1) * 128, tid, b, bh,
                            kh, kl, vth, vtl, mask);
        CP_COMMIT();

        uint32_t stg = sb + AT_STG + (jt & 1) * 65536;
        const float* maskS = (const float*)(smem + AT_MASK + (jt & 1) * 512);

        // ---- S = Q K^T : fused (Qh+Ql)*Kh pass + Qh*Kl pass ----
        float s[16][4];
#pragma unroll
        for (int nt = 0; nt < 16; nt++)
#pragma unroll
            for (int v = 0; v < 4; v++) s[nt][v] = 0.0f;

#pragma unroll
        for (int ks = 0; ks < 4; ks++) {
            const uint32_t kb = (uint32_t)(ks * 32 + khalf);
#pragma unroll
            for (int np = 0; np < 8; np++) {
                uint32_t b4[4];
                LDSM4(b4[0], b4[1], b4[2], b4[3],
                      stg + AT_KH + SWZ128((uint32_t)((np * 16 + l16) * 128) + kb));
                MMA16816(s[np * 2],     qfh[ks], b4[0], b4[2]);
                MMA16816(s[np * 2 + 1], qfh[ks], b4[1], b4[3]);
                MMA16816(s[np * 2],     qfl[ks], b4[0], b4[2]);
                MMA16816(s[np * 2 + 1], qfl[ks], b4[1], b4[3]);
            }
        }
#pragma unroll
        for (int ks = 0; ks < 4; ks++) {
            const uint32_t kb = (uint32_t)(ks * 32 + khalf);
#pragma unroll
            for (int np = 0; np < 8; np++) {
                uint32_t b4[4];
                LDSM4(b4[0], b4[1], b4[2], b4[3],
                      stg + AT_KL + SWZ128((uint32_t)((np * 16 + l16) * 128) + kb));
                MMA16816(s[np * 2],     qfh[ks], b4[0], b4[2]);
                MMA16816(s[np * 2 + 1], qfh[ks], b4[1], b4[3]);
            }
        }

        // ---- mask*scale*log2e, online softmax (log2 domain) ----
        float rm0 = -1e30f, rm1 = -1e30f;
#pragma unroll
        for (int nt = 0; nt < 16; nt++) {
            float2 mk = *(const float2*)&maskS[nt * 8 + t4 * 2];
            mk.x *= MSC; mk.y *= MSC;
            s[nt][0] *= mk.x; s[nt][1] *= mk.y;
            s[nt][2] *= mk.x; s[nt][3] *= mk.y;
            rm0 = fmaxf(rm0, fmaxf(s[nt][0], s[nt][1]));
            rm1 = fmaxf(rm1, fmaxf(s[nt][2], s[nt][3]));
        }
        rm0 = fmaxf(rm0, __shfl_xor_sync(0xffffffffu, rm0, 1));
        rm0 = fmaxf(rm0, __shfl_xor_sync(0xffffffffu, rm0, 2));
        rm1 = fmaxf(rm1, __shfl_xor_sync(0xffffffffu, rm1, 1));
        rm1 = fmaxf(rm1, __shfl_xor_sync(0xffffffffu, rm1, 2));
        float mn0 = fmaxf(m0, rm0), mn1 = fmaxf(m1, rm1);
        float al0 = exp2f(m0 - mn0), al1 = exp2f(m1 - mn1);
        m0 = mn0; m1 = mn1;
        lsum0 *= al0; lsum1 *= al1;
#pragma unroll
        for (int nt = 0; nt < 8; nt++) {
            o[nt][0] *= al0; o[nt][1] *= al0;
            o[nt][2] *= al1; o[nt][3] *= al1;
        }
        float ps0 = 0.0f, ps1 = 0.0f;
#pragma unroll
        for (int nt = 0; nt < 16; nt++) {
            s[nt][0] = exp2f(s[nt][0] - m0);
            s[nt][1] = exp2f(s[nt][1] - m0);
            s[nt][2] = exp2f(s[nt][2] - m1);
            s[nt][3] = exp2f(s[nt][3] - m1);
            ps0 += s[nt][0] + s[nt][1];
            ps1 += s[nt][2] + s[nt][3];
        }
        lsum0 += ps0; lsum1 += ps1;

        // ---- pack P fragments (S accum frag == A operand frag layout) ----
        uint32_t ph[8][4], pl[8][4];
#pragma unroll
        for (int ks = 0; ks < 8; ks++) {
            split2(s[2 * ks][0],     s[2 * ks][1],     ph[ks][0], pl[ks][0]);
            split2(s[2 * ks][2],     s[2 * ks][3],     ph[ks][1], pl[ks][1]);
            split2(s[2 * ks + 1][0], s[2 * ks + 1][1], ph[ks][2], pl[ks][2]);
            split2(s[2 * ks + 1][2], s[2 * ks + 1][3], ph[ks][3], pl[ks][3]);
        }

        // ---- O += P V : fused (Ph+Pl)*Vh pass + Ph*Vl pass ----
#pragma unroll
        for (int ks = 0; ks < 8; ks++) {
            const uint32_t kb = (uint32_t)(ks * 32 + khalf);
#pragma unroll
            for (int np = 0; np < 4; np++) {
                uint32_t b4[4];
                LDSM4(b4[0], b4[1], b4[2], b4[3],
                      stg + AT_VH + SWZ256((uint32_t)((np * 16 + l16) * 256) + kb));
                MMA16816(o[np * 2],     ph[ks], b4[0], b4[2]);
                MMA16816(o[np * 2 + 1], ph[ks], b4[1], b4[3]);
                MMA16816(o[np * 2],     pl[ks], b4[0], b4[2]);
                MMA16816(o[np * 2 + 1], pl[ks], b4[1], b4[3]);
            }
        }
#pragma unroll
        for (int ks = 0; ks < 8; ks++) {
            const uint32_t kb = (uint32_t)(ks * 32 + khalf);
#pragma unroll
            for (int np = 0; np < 4; np++) {
                uint32_t b4[4];
                LDSM4(b4[0], b4[1], b4[2], b4[3],
                      stg + AT_VL + SWZ256((uint32_t)((np * 16 + l16) * 256) + kb));
                MMA16816(o[np * 2],     ph[ks], b4[0], b4[2]);
                MMA16816(o[np * 2 + 1], ph[ks], b4[1], b4[3]);
            }
        }
    }

    // ---- finalize: reduce l over quad, normalize, write split A' for GEMM3 ----
    lsum0 += __shfl_xor_sync(0xffffffffu, lsum0, 1);
    lsum0 += __shfl_xor_sync(0xffffffffu, lsum0, 2);
    lsum1 += __shfl_xor_sync(0xffffffffu, lsum1, 1);
    lsum1 += __shfl_xor_sync(0xffffffffu, lsum1, 2);
    float inv0 = 1.0f / lsum0, inv1 = 1.0f / lsum1;

    const int r0 = i0 + w * 16 + g, r1 = r0 + 8;
#pragma unroll
    for (int nt = 0; nt < 8; nt++) {
        int col = nt * 8 + t4 * 2;
        uint32_t hi, lo;
        size_t base0 = (size_t)(b * SEQ + r0) * KP + h * 64 + col;
        split2(o[nt][0] * inv0, o[nt][1] * inv0, hi, lo);
        *(uint32_t*)&a2q[base0]        = hi;
        *(uint32_t*)&a2q[base0 + 1024] = hi;
        *(uint32_t*)&a2q[base0 + 2048] = lo;
        size_t base1 = (size_t)(b * SEQ + r1) * KP + h * 64 + col;
        split2(o[nt][2] * inv1, o[nt][3] * inv1, hi, lo);
        *(uint32_t*)&a2q[base1]        = hi;
        *(uint32_t*)&a2q[base1 + 1024] = hi;
        *(uint32_t*)&a2q[base1 + 2048] = lo;
    }
}

// ---------------------------------------------------------------------------
// Launch
// ---------------------------------------------------------------------------
extern "C" void kernel_launch(void* const* d_in, const int* in_sizes, int n_in,
                              void* d_out, int out_size)
{
    const float* x     = (const float*)d_in[0];
    const float* smask = (const float*)d_in[1];
    const float* wqkv  = (const float*)d_in[2];
    const float* wout  = (const float*)d_in[3];
    float* out = (float*)d_out;

    __nv_bfloat16 *aq, *wq, *wo, *a2q, *qhp, *qlp, *khp, *klp, *vthp, *vtlp;
    float* vstp;
    cudaGetSymbolAddress((void**)&aq,  g_Aq);
    cudaGetSymbolAddress((void**)&wq,  g_Wq);
    cudaGetSymbolAddress((void**)&wo,  g_Wo);
    cudaGetSymbolAddress((void**)&a2q, g_A2q);
    cudaGetSymbolAddress((void**)&qhp, g_qh);
    cudaGetSymbolAddress((void**)&qlp, g_ql);
    cudaGetSymbolAddress((void**)&khp, g_kh);
    cudaGetSymbolAddress((void**)&klp, g_kl);
    cudaGetSymbolAddress((void**)&vthp, g_vth);
    cudaGetSymbolAddress((void**)&vtlp, g_vtl);
    cudaGetSymbolAddress((void**)&vstp, g_vst);

    cudaFuncSetAttribute(mma_gemm_kernel, cudaFuncAttributeMaxDynamicSharedMemorySize,
                         GSMEM_BYTES);
    cudaFuncSetAttribute(attn_mma_kernel, cudaFuncAttributeMaxDynamicSharedMemorySize,
                         AT_SMEM);

    // 0) split inputs
    split_a_kernel<<<MROWS * 1024 / 256, 256>>>(x, aq, MROWS);
    split_w_kernel<<<dim3(QKV_COLS / 32, 32), dim3(32, 8)>>>(wqkv, wq, QKV_COLS);
    split_w_kernel<<<dim3(DIM / 32, 32), dim3(32, 8)>>>(wout, wo, DIM);

    // 1) qkv GEMM, epilogue splits Q/K to bf16 and stages V fp32
    mma_gemm_kernel<<<dim3(QKV_COLS / 128, MROWS / 128), 256, GSMEM_BYTES>>>(
        aq, wq, nullptr, QKV_COLS, 1, qhp, qlp, khp, klp, vstp);

    // 1b) V transpose + split
    split_vt_kernel<<<dim3(SEQ / 32, 2, 32), dim3(32, 8)>>>(vstp, vthp, vtlp);

    // 2) flash attention on tensor pipe; epilogue writes split A' for GEMM3
    attn_mma_kernel<<<dim3(SEQ / 128, BATCH * HEADS), 256, AT_SMEM>>>(
        qhp, qlp, khp, klp, vthp, vtlp, smask, a2q);

    // 3) out projection
    mma_gemm_kernel<<<dim3(DIM / 128, MROWS / 128), 256, GSMEM_BYTES>>>(
        a2q, wo, out, DIM, 0, nullptr, nullptr, nullptr, nullptr, nullptr);
}